// round 1
// baseline (speedup 1.0000x reference)
#include <cuda_runtime.h>
#include <math.h>

// ---------------- problem constants ----------------
#define NB   64          // batch
#define NC   512         // channels
#define NT   128         // time
#define NV   1024        // codebook entries
#define NQ   8           // scales
#define NIDX 255         // sum of scales
#define NELEM (NB*NC*NT) // 4194304

// ---------------- device scratch (static, allowed) ----------------
__device__ float g_zq[NELEM];
__device__ float g_zhat[NELEM];
__device__ float g_xd[NB*NC*NT];      // max s=128
__device__ float g_up[NELEM];
__device__ float g_h[NELEM];
__device__ float g_zhq[NELEM];
__device__ float g_cnorm[NQ*NV];
__device__ unsigned long long g_bestkey[NB*NT];
__device__ int   g_idxbuf[NB*NIDX];
__device__ int   g_counts[NV];
__device__ float g_partial[2048];
__device__ float g_sums[3];           // usage, loss, perp accumulators

// ---------------- init ----------------
__global__ void init_kernel(const float* __restrict__ z) {
    long long stride = (long long)gridDim.x * blockDim.x;
    long long t0 = (long long)blockIdx.x * blockDim.x + threadIdx.x;
    for (long long i = t0; i < NELEM; i += stride) {
        g_zq[i] = z[i];
        g_zhat[i] = 0.0f;
    }
    if (t0 < 3)  g_sums[t0] = 0.0f;
    if (t0 < NV) g_counts[t0] = 0;
    if (t0 < NB*NT) g_bestkey[t0] = ~0ULL;
}

// ---------------- codebook norms: one block per (q,v) row ----------------
__global__ void cnorm_kernel(const float* __restrict__ cb) {
    int row = blockIdx.x;                 // q*NV + v
    const float* p = cb + (long long)row * NC;
    float s = 0.0f;
    for (int c = threadIdx.x; c < NC; c += 128) {
        float x = p[c];
        s += x * x;
    }
    __shared__ float sh[4];
    for (int o = 16; o > 0; o >>= 1) s += __shfl_down_sync(0xffffffffu, s, o);
    if ((threadIdx.x & 31) == 0) sh[threadIdx.x >> 5] = s;
    __syncthreads();
    if (threadIdx.x == 0)
        g_cnorm[row] = sh[0] + sh[1] + sh[2] + sh[3];
}

// ---------------- downsample: window mean of g_zq -> g_xd ----------------
__global__ void downsample_kernel(int s, int slog) {
    int total = NB * NC * s;
    int r = NT >> slog;
    int i = blockIdx.x * blockDim.x + threadIdx.x;
    if (i >= total) return;
    int j  = i & (s - 1);
    int bc = i >> slog;
    const float* src = g_zq + (long long)bc * NT + j * r;
    float acc = 0.0f;
    for (int k = 0; k < r; k++) acc += src[k];
    g_xd[i] = acc * (1.0f / (float)r);
}

// ---------------- quantize: tiled GEMM (xd @ cb^T) + fused argmin ----------------
// grid: (ceil(M/128), 4 code-splits of 256 codes). block 256 threads.
// score(v) = cnorm[v] - 2*dot  (same ordering as ||x||^2 - 2x.c + ||c||^2)
__global__ __launch_bounds__(256) void quantize_kernel(
    const float* __restrict__ cb, int q, int s, int slog)
{
    const int M  = NB * s;
    const int m0 = blockIdx.x * 128;
    const int nbase = blockIdx.y * 256;
    __shared__ float As[128][33];
    __shared__ float Bs[128][33];

    const int tid = threadIdx.x;
    const int ti = tid >> 4;   // 0..15
    const int tj = tid & 15;   // 0..15

    float bestv[8];
    int   besti[8];
#pragma unroll
    for (int r = 0; r < 8; r++) { bestv[r] = INFINITY; besti[r] = 0; }

    for (int nc = 0; nc < 2; nc++) {
        const int n0 = nbase + nc * 128;
        float acc[8][8];
#pragma unroll
        for (int r = 0; r < 8; r++)
#pragma unroll
            for (int c2 = 0; c2 < 8; c2++) acc[r][c2] = 0.0f;

        for (int kc = 0; kc < NC; kc += 32) {
            // load A tile (coalesced in m -> contiguous j for large s)
#pragma unroll
            for (int it = 0; it < 16; it++) {
                int e = tid + 256 * it;
                int m = e & 127, kk = e >> 7;
                int gm = m0 + m;
                float v = 0.0f;
                if (gm < M) {
                    int b = gm >> slog;
                    int j = gm & (s - 1);
                    v = g_xd[(((long long)b * NC + (kc + kk)) << slog) + j];
                }
                As[m][kk] = v;
            }
            // load B tile (coalesced in k)
#pragma unroll
            for (int it = 0; it < 16; it++) {
                int e = tid + 256 * it;
                int kk = e & 31, n = e >> 5;
                Bs[n][kk] = cb[(long long)(n0 + n) * NC + kc + kk];
            }
            __syncthreads();
#pragma unroll
            for (int kk = 0; kk < 32; kk++) {
                float a[8], bv[8];
#pragma unroll
                for (int r = 0; r < 8; r++)  a[r]  = As[r * 16 + ti][kk];
#pragma unroll
                for (int c2 = 0; c2 < 8; c2++) bv[c2] = Bs[c2 * 16 + tj][kk];
#pragma unroll
                for (int r = 0; r < 8; r++)
#pragma unroll
                    for (int c2 = 0; c2 < 8; c2++)
                        acc[r][c2] += a[r] * bv[c2];
            }
            __syncthreads();
        }
        // scores + per-thread running argmin (thread's code ids increase -> strict < keeps first)
#pragma unroll
        for (int c2 = 0; c2 < 8; c2++) {
            int n = n0 + c2 * 16 + tj;
            float cn = g_cnorm[q * NV + n];
#pragma unroll
            for (int r = 0; r < 8; r++) {
                float sc = cn - 2.0f * acc[r][c2];
                if (sc < bestv[r]) { bestv[r] = sc; besti[r] = n; }
            }
        }
    }
    // reduce over tj (16-lane groups) then atomicMin on packed key
#pragma unroll
    for (int r = 0; r < 8; r++) {
        float v = bestv[r];
        int   ix = besti[r];
        for (int off = 8; off > 0; off >>= 1) {
            float ov = __shfl_down_sync(0xffffffffu, v, off, 16);
            int   oi = __shfl_down_sync(0xffffffffu, ix, off, 16);
            if (ov < v || (ov == v && oi < ix)) { v = ov; ix = oi; }
        }
        if (tj == 0) {
            int gm = m0 + r * 16 + ti;
            if (gm < M) {
                unsigned u = __float_as_uint(v);
                u = (u & 0x80000000u) ? ~u : (u | 0x80000000u);
                unsigned long long key = ((unsigned long long)u << 32) | (unsigned)ix;
                atomicMin(&g_bestkey[gm], key);
            }
        }
    }
}

// ---------------- extract idx, histogram ----------------
__global__ void post_quantize_kernel(int s, int slog) {
    int m = blockIdx.x * blockDim.x + threadIdx.x;
    int M = NB * s;
    if (m >= M) return;
    int v = (int)(g_bestkey[m] & 0xFFFFFFFFULL);
    int b = m >> slog;
    int j = m & (s - 1);
    g_idxbuf[b * NIDX + (s - 1) + j] = v;
    atomicAdd(&g_counts[v], 1);
}

// ---------------- gather codebook + linear upsample (half-pixel, clamped) ----------------
__global__ void upsample_kernel(const float* __restrict__ cb, int s) {
    int b = blockIdx.x;
    int t = blockIdx.y;
    float u = (t + 0.5f) * ((float)s / 128.0f) - 0.5f;
    float jf = floorf(u);
    float f = u - jf;
    int j0 = (int)jf;
    int j1 = j0 + 1;
    if (j0 < 0) j0 = 0; if (j0 > s - 1) j0 = s - 1;
    if (j1 < 0) j1 = 0; if (j1 > s - 1) j1 = s - 1;
    int v0 = g_idxbuf[b * NIDX + (s - 1) + j0];
    int v1 = g_idxbuf[b * NIDX + (s - 1) + j1];
    const float* c0 = cb + (long long)v0 * NC;
    const float* c1 = cb + (long long)v1 * NC;
    float w1 = f, w0 = 1.0f - f;
    for (int c = threadIdx.x; c < NC; c += 128) {
        g_up[((long long)b * NC + c) * NT + t] = w0 * c0[c] + w1 * c1[c];
    }
}

// ---------------- direct conv1d (C=512->512, K=3, same pad) + bias + ReLU ----------------
// grid (8 co-tiles, B). block 128. each thread: 8 co x 8 t. FMA:LDS = 4:1.
__global__ __launch_bounds__(128) void conv_relu_kernel(
    const float* __restrict__ x, const float* __restrict__ w,
    const float* __restrict__ bias, float* __restrict__ y)
{
    const int b = blockIdx.y;
    const int co0 = blockIdx.x * 64;
    __shared__ float xs[32][130];
    __shared__ float ws[64][97];   // [co][ci*3+k], padded pitch (odd mult of 32+1)

    const int tid = threadIdx.x;
    const int cg = tid >> 4;   // 0..7 -> co group
    const int tg = tid & 15;   // 0..15 -> t = tg + 16u

    float acc[8][8];
#pragma unroll
    for (int cc = 0; cc < 8; cc++)
#pragma unroll
        for (int u = 0; u < 8; u++) acc[cc][u] = 0.0f;

    for (int ci0 = 0; ci0 < NC; ci0 += 32) {
        for (int e = tid; e < 32 * 130; e += 128) {
            int ci = e / 130, tt = e % 130;
            int t = tt - 1;
            float v = 0.0f;
            if (t >= 0 && t < NT)
                v = x[((long long)b * NC + ci0 + ci) * NT + t];
            xs[ci][tt] = v;
        }
        for (int e = tid; e < 64 * 96; e += 128) {
            int co = e / 96, rem = e % 96;
            ws[co][rem] = w[(long long)(co0 + co) * (NC * 3) + (long long)ci0 * 3 + rem];
        }
        __syncthreads();
#pragma unroll 4
        for (int ci = 0; ci < 32; ci++) {
            float wr[8][3];
#pragma unroll
            for (int cc = 0; cc < 8; cc++)
#pragma unroll
                for (int k = 0; k < 3; k++)
                    wr[cc][k] = ws[cg * 8 + cc][ci * 3 + k];
#pragma unroll
            for (int u = 0; u < 8; u++) {
                int t = tg + 16 * u;
                float x0 = xs[ci][t];
                float x1 = xs[ci][t + 1];
                float x2 = xs[ci][t + 2];
#pragma unroll
                for (int cc = 0; cc < 8; cc++)
                    acc[cc][u] += wr[cc][0] * x0 + wr[cc][1] * x1 + wr[cc][2] * x2;
            }
        }
        __syncthreads();
    }
#pragma unroll
    for (int cc = 0; cc < 8; cc++) {
        float bv = bias[co0 + cg * 8 + cc];
#pragma unroll
        for (int u = 0; u < 8; u++) {
            float v = acc[cc][u] + bv;
            y[((long long)b * NC + co0 + cg * 8 + cc) * NT + tg + 16 * u] = fmaxf(v, 0.0f);
        }
    }
}

// ---------------- residual update + per-block loss partials ----------------
__global__ void update_loss_kernel(const float* __restrict__ z) {
    __shared__ float sh[8];
    float local = 0.0f;
    long long stride = (long long)gridDim.x * blockDim.x;
    for (long long i = (long long)blockIdx.x * blockDim.x + threadIdx.x; i < NELEM; i += stride) {
        float hq = g_zhq[i];
        float zh = g_zhat[i] + hq;
        g_zhat[i] = zh;
        g_zq[i] -= hq;
        float d = zh - z[i];
        local += d * d;
    }
    for (int o = 16; o > 0; o >>= 1) local += __shfl_down_sync(0xffffffffu, local, o);
    if ((threadIdx.x & 31) == 0) sh[threadIdx.x >> 5] = local;
    __syncthreads();
    if (threadIdx.x == 0) {
        float s = 0.0f;
        for (int w = 0; w < (int)(blockDim.x >> 5); w++) s += sh[w];
        g_partial[blockIdx.x] = s;
    }
}

// ---------------- per-scale finalize: loss/usage/perp, accumulate, reset ----------------
__global__ void finalize_kernel(int s) {
    __shared__ float sh[32];
    int tid = threadIdx.x;

    // loss partials
    float lsum = 0.0f;
    for (int i = tid; i < 2048; i += 1024) lsum += g_partial[i];
    for (int o = 16; o > 0; o >>= 1) lsum += __shfl_down_sync(0xffffffffu, lsum, o);
    if ((tid & 31) == 0) sh[tid >> 5] = lsum;
    __syncthreads();
    float loss_total = 0.0f;
    if (tid == 0) { for (int w = 0; w < 32; w++) loss_total += sh[w]; }
    __syncthreads();

    // histogram stats (V == blockDim == 1024)
    int c = g_counts[tid];
    float used = (c > 0) ? 1.0f : 0.0f;
    float p = (float)c / (float)(NB * s);
    float ent = p * logf(p + 1e-10f);

    float us = used;
    for (int o = 16; o > 0; o >>= 1) us += __shfl_down_sync(0xffffffffu, us, o);
    if ((tid & 31) == 0) sh[tid >> 5] = us;
    __syncthreads();
    float used_total = 0.0f;
    if (tid == 0) { for (int w = 0; w < 32; w++) used_total += sh[w]; }
    __syncthreads();

    float es = ent;
    for (int o = 16; o > 0; o >>= 1) es += __shfl_down_sync(0xffffffffu, es, o);
    if ((tid & 31) == 0) sh[tid >> 5] = es;
    __syncthreads();
    float ent_total = 0.0f;
    if (tid == 0) { for (int w = 0; w < 32; w++) ent_total += sh[w]; }

    if (tid == 0) {
        g_sums[0] += used_total * (100.0f / (float)NV);
        g_sums[1] += 1.25f * loss_total / (float)NELEM;   // (1+BETA)*MSE
        g_sums[2] += expf(-ent_total);
    }
    // reset for next scale
    g_counts[tid] = 0;
    for (int i = tid; i < NB * NT; i += 1024) g_bestkey[i] = ~0ULL;
}

// ---------------- write outputs ----------------
// layout: [z_hat (NELEM)] [usage] [loss] [perp] [indices as float (NB*NIDX)]
__global__ void writeout_kernel(float* __restrict__ out, int out_size) {
    long long stride = (long long)gridDim.x * blockDim.x;
    long long t0 = (long long)blockIdx.x * blockDim.x + threadIdx.x;
    for (long long i = t0; i < NELEM && i < out_size; i += stride)
        out[i] = g_zhat[i];
    if (t0 == 0) {
        if (NELEM + 0 < out_size) out[NELEM + 0] = g_sums[0] / 8.0f;
        if (NELEM + 1 < out_size) out[NELEM + 1] = g_sums[1] / 8.0f;
        if (NELEM + 2 < out_size) out[NELEM + 2] = g_sums[2] / 8.0f;
    }
    if (t0 < NB * NIDX && NELEM + 3 + t0 < out_size)
        out[NELEM + 3 + t0] = (float)g_idxbuf[t0];
}

// ---------------- host launch sequence (graph-capturable) ----------------
extern "C" void kernel_launch(void* const* d_in, const int* in_sizes, int n_in,
                              void* d_out, int out_size) {
    const float* z  = (const float*)d_in[0];
    const float* cb = (const float*)d_in[1];
    const float* pw = (const float*)d_in[2];
    const float* pb = (const float*)d_in[3];
    float* out = (float*)d_out;

    void *p_up = 0, *p_h = 0, *p_zhq = 0;
    cudaGetSymbolAddress(&p_up,  g_up);
    cudaGetSymbolAddress(&p_h,   g_h);
    cudaGetSymbolAddress(&p_zhq, g_zhq);

    init_kernel<<<2048, 256>>>(z);
    cnorm_kernel<<<NQ * NV, 128>>>(cb);

    for (int q = 0; q < NQ; q++) {
        int s = 1 << q;
        int slog = q;
        int M = NB * s;
        const float* cbq = cb + (long long)q * NV * NC;

        downsample_kernel<<<(NB * NC * s + 255) / 256, 256>>>(s, slog);

        dim3 qg((M + 127) / 128, 4);
        quantize_kernel<<<qg, 256>>>(cbq, q, s, slog);
        post_quantize_kernel<<<(M + 255) / 256, 256>>>(s, slog);

        upsample_kernel<<<dim3(NB, NT), 128>>>(cbq, s);

        const float* w0 = pw + ((long long)q * 2 + 0) * NC * NC * 3;
        const float* w1 = pw + ((long long)q * 2 + 1) * NC * NC * 3;
        const float* b0 = pb + ((long long)q * 2 + 0) * NC;
        const float* b1 = pb + ((long long)q * 2 + 1) * NC;
        conv_relu_kernel<<<dim3(8, NB), 128>>>((const float*)p_up, w0, b0, (float*)p_h);
        conv_relu_kernel<<<dim3(8, NB), 128>>>((const float*)p_h,  w1, b1, (float*)p_zhq);

        update_loss_kernel<<<2048, 256>>>(z);
        finalize_kernel<<<1, 1024>>>(s);
    }

    writeout_kernel<<<2048, 256>>>(out, out_size);
}

// round 2
// speedup vs baseline: 1.0847x; 1.0847x over previous
#include <cuda_runtime.h>
#include <math.h>

// ---------------- problem constants ----------------
#define NB   64          // batch
#define NC   512         // channels
#define NT   128         // time
#define NV   1024        // codebook entries
#define NQ   8           // scales
#define NIDX 255         // sum of scales
#define NELEM (NB*NC*NT) // 4194304

// ---------------- device scratch ----------------
__device__ float g_zq[NELEM];
__device__ float g_zhat[NELEM];
__device__ float g_xd[NB*NC*NT];
__device__ float g_up[NELEM];
__device__ float g_h[NELEM];
__device__ float g_wT[16ll*1536*512];      // transposed conv weights [q*2+d][ci*3+k][co]
__device__ float g_cnorm[NQ*NV];
__device__ unsigned long long g_bestkey[NB*NT];
__device__ int   g_idxbuf[NB*NIDX];
__device__ int   g_counts[NV];
__device__ float g_partial[512];
__device__ float g_sums[3];

// ---------------- f32x2 helpers ----------------
__device__ __forceinline__ unsigned long long dup2(float x) {
    unsigned long long r;
    asm("mov.b64 %0, {%1, %1};" : "=l"(r) : "f"(x));
    return r;
}
__device__ __forceinline__ void fma2(unsigned long long& a, unsigned long long x, unsigned long long y) {
    asm("fma.rn.f32x2 %0, %1, %2, %0;" : "+l"(a) : "l"(x), "l"(y));
}
__device__ __forceinline__ float2 unpack2(unsigned long long v) {
    float2 f;
    asm("mov.b64 {%0, %1}, %2;" : "=f"(f.x), "=f"(f.y) : "l"(v));
    return f;
}

// ---------------- init ----------------
__global__ void init_kernel(const float* __restrict__ z) {
    long long stride = (long long)gridDim.x * blockDim.x;
    long long t0 = (long long)blockIdx.x * blockDim.x + threadIdx.x;
    for (long long i = t0; i < NELEM; i += stride) {
        g_zq[i] = z[i];
        g_zhat[i] = 0.0f;
    }
    if (t0 < 3)  g_sums[t0] = 0.0f;
    if (t0 < NV) g_counts[t0] = 0;
    if (t0 < NB*NT) g_bestkey[t0] = ~0ULL;
}

// ---------------- weight transpose: w[qd][co][ci3] -> g_wT[qd][ci3][co] ----------------
__global__ void wtrans_kernel(const float* __restrict__ w) {
    __shared__ float tile[32][33];
    int qd  = blockIdx.z;
    int ci0 = blockIdx.x * 32;
    int co0 = blockIdx.y * 32;
    const float* src = w + (long long)qd * 512 * 1536;
    for (int r = threadIdx.y; r < 32; r += 8)
        tile[r][threadIdx.x] = src[(long long)(co0 + r) * 1536 + ci0 + threadIdx.x];
    __syncthreads();
    float* dst = g_wT + (long long)qd * 1536 * 512;
    for (int r = threadIdx.y; r < 32; r += 8)
        dst[(long long)(ci0 + r) * 512 + co0 + threadIdx.x] = tile[threadIdx.x][r];
}

// ---------------- codebook norms ----------------
__global__ void cnorm_kernel(const float* __restrict__ cb) {
    int row = blockIdx.x;
    const float* p = cb + (long long)row * NC;
    float s = 0.0f;
    for (int c = threadIdx.x; c < NC; c += 128) {
        float x = p[c];
        s += x * x;
    }
    __shared__ float sh[4];
    for (int o = 16; o > 0; o >>= 1) s += __shfl_down_sync(0xffffffffu, s, o);
    if ((threadIdx.x & 31) == 0) sh[threadIdx.x >> 5] = s;
    __syncthreads();
    if (threadIdx.x == 0)
        g_cnorm[row] = sh[0] + sh[1] + sh[2] + sh[3];
}

// ---------------- downsample ----------------
__global__ void downsample_kernel(int s, int slog) {
    int total = NB * NC * s;
    int r = NT >> slog;
    int i = blockIdx.x * blockDim.x + threadIdx.x;
    if (i >= total) return;
    int j  = i & (s - 1);
    int bc = i >> slog;
    const float* src = g_zq + (long long)bc * NT + j * r;
    float acc = 0.0f;
    for (int k = 0; k < r; k++) acc += src[k];
    g_xd[i] = acc * (1.0f / (float)r);
}

// ---------------- quantize (small s): grid (64, 8), block 256 ----------------
// Block (b, code-chunk of 128). Each warp: 16 codes. Lane handles dims d = lane + 32e.
template<int S>
__global__ __launch_bounds__(256) void quantize_small_kernel(const float* __restrict__ cb, int q) {
    __shared__ float xs[S][512];
    int b  = blockIdx.x;
    int c0 = blockIdx.y * 128;
    int tid = threadIdx.x;

    for (int e = tid; e < S * 512; e += 256) {
        int j = e >> 9, ch = e & 511;
        xs[j][ch] = g_xd[(b * 512 + ch) * S + j];
    }
    __syncthreads();

    int w = tid >> 5, lane = tid & 31;
    float bestv[S];
    int   besti[S];
#pragma unroll
    for (int j = 0; j < S; j++) { bestv[j] = INFINITY; besti[j] = 0; }

    for (int cc = 0; cc < 16; cc++) {
        int code = c0 + w * 16 + cc;
        const float* cbr = cb + (long long)code * 512;
        float cv[16];
#pragma unroll
        for (int e = 0; e < 16; e++) cv[e] = cbr[lane + 32 * e];
        float cn = g_cnorm[q * NV + code];
#pragma unroll
        for (int j = 0; j < S; j++) {
            float d = 0.0f;
#pragma unroll
            for (int e = 0; e < 16; e++) d += xs[j][lane + 32 * e] * cv[e];
            for (int o = 16; o > 0; o >>= 1) d += __shfl_xor_sync(0xffffffffu, d, o);
            float sc = cn - 2.0f * d;
            if (sc < bestv[j]) { bestv[j] = sc; besti[j] = code; }
        }
    }
    if (lane == 0) {
#pragma unroll
        for (int j = 0; j < S; j++) {
            unsigned u = __float_as_uint(bestv[j]);
            u = (u & 0x80000000u) ? ~u : (u | 0x80000000u);
            unsigned long long key = ((unsigned long long)u << 32) | (unsigned)besti[j];
            atomicMin(&g_bestkey[b * S + j], key);
        }
    }
}

// ---------------- quantize (large s): 64m x 128n tile GEMM w/ f32x2 + fused argmin ----------------
// grid (M/64, 8), block 256. Thread: m = ti+16r (r<4), n pairs (2tj+32c, +1) (c<4).
__global__ __launch_bounds__(256) void quantize_gemm_kernel(
    const float* __restrict__ cb, int q, int s, int slog)
{
    const int m0 = blockIdx.x * 64;
    const int n0 = blockIdx.y * 128;
    __shared__ float As[32][65];
    __shared__ float Bs[32][130];

    const int tid = threadIdx.x;
    const int ti = tid >> 4;   // 0..15
    const int tj = tid & 15;   // 0..15

    unsigned long long acc[4][4];
#pragma unroll
    for (int r = 0; r < 4; r++)
#pragma unroll
        for (int c = 0; c < 4; c++) acc[r][c] = 0ULL;

    for (int kc = 0; kc < NC; kc += 32) {
#pragma unroll
        for (int it = 0; it < 8; it++) {
            int e = tid + 256 * it;   // e < 2048
            int m = e & 63, kk = e >> 6;
            int gm = m0 + m;
            int b = gm >> slog;
            int j = gm & (s - 1);
            As[kk][m] = g_xd[(((long long)b * NC + (kc + kk)) << slog) + j];
        }
#pragma unroll
        for (int it = 0; it < 16; it++) {
            int e = tid + 256 * it;   // e < 4096
            int kk = e & 31, n = e >> 5;
            Bs[kk][n] = cb[(long long)(n0 + n) * NC + kc + kk];
        }
        __syncthreads();
#pragma unroll 8
        for (int kk = 0; kk < 32; kk++) {
            unsigned long long a2[4], b2[4];
#pragma unroll
            for (int r = 0; r < 4; r++) a2[r] = dup2(As[kk][ti + 16 * r]);
#pragma unroll
            for (int c = 0; c < 4; c++)
                b2[c] = *(const unsigned long long*)&Bs[kk][2 * tj + 32 * c];
#pragma unroll
            for (int r = 0; r < 4; r++)
#pragma unroll
                for (int c = 0; c < 4; c++)
                    fma2(acc[r][c], a2[r], b2[c]);
        }
        __syncthreads();
    }

    float bestv[4];
    int   besti[4];
#pragma unroll
    for (int r = 0; r < 4; r++) { bestv[r] = INFINITY; besti[r] = 0; }
#pragma unroll
    for (int c = 0; c < 4; c++) {
        int n = n0 + 2 * tj + 32 * c;
        float cn0 = g_cnorm[q * NV + n];
        float cn1 = g_cnorm[q * NV + n + 1];
#pragma unroll
        for (int r = 0; r < 4; r++) {
            float2 dv = unpack2(acc[r][c]);
            float s0 = cn0 - 2.0f * dv.x;
            float s1 = cn1 - 2.0f * dv.y;
            if (s0 < bestv[r]) { bestv[r] = s0; besti[r] = n; }
            if (s1 < bestv[r]) { bestv[r] = s1; besti[r] = n + 1; }
        }
    }
#pragma unroll
    for (int r = 0; r < 4; r++) {
        float v = bestv[r];
        int   ix = besti[r];
        for (int off = 8; off > 0; off >>= 1) {
            float ov = __shfl_down_sync(0xffffffffu, v, off, 16);
            int   oi = __shfl_down_sync(0xffffffffu, ix, off, 16);
            if (ov < v || (ov == v && oi < ix)) { v = ov; ix = oi; }
        }
        if (tj == 0) {
            int gm = m0 + ti + 16 * r;
            unsigned u = __float_as_uint(v);
            u = (u & 0x80000000u) ? ~u : (u | 0x80000000u);
            unsigned long long key = ((unsigned long long)u << 32) | (unsigned)ix;
            atomicMin(&g_bestkey[gm], key);
        }
    }
}

// ---------------- extract idx, histogram ----------------
__global__ void post_quantize_kernel(int s, int slog) {
    int m = blockIdx.x * blockDim.x + threadIdx.x;
    int M = NB * s;
    if (m >= M) return;
    int v = (int)(g_bestkey[m] & 0xFFFFFFFFULL);
    int b = m >> slog;
    int j = m & (s - 1);
    g_idxbuf[b * NIDX + (s - 1) + j] = v;
    atomicAdd(&g_counts[v], 1);
}

// ---------------- gather + linear upsample ----------------
__global__ void upsample_kernel(const float* __restrict__ cb, int s) {
    int b = blockIdx.x;
    int t = blockIdx.y;
    float u = (t + 0.5f) * ((float)s / 128.0f) - 0.5f;
    float jf = floorf(u);
    float f = u - jf;
    int j0 = (int)jf;
    int j1 = j0 + 1;
    if (j0 < 0) j0 = 0; if (j0 > s - 1) j0 = s - 1;
    if (j1 < 0) j1 = 0; if (j1 > s - 1) j1 = s - 1;
    int v0 = g_idxbuf[b * NIDX + (s - 1) + j0];
    int v1 = g_idxbuf[b * NIDX + (s - 1) + j1];
    const float* c0 = cb + (long long)v0 * NC;
    const float* c1 = cb + (long long)v1 * NC;
    float w1 = f, w0 = 1.0f - f;
    for (int c = threadIdx.x; c < NC; c += 128) {
        g_up[((long long)b * NC + c) * NT + t] = w0 * c0[c] + w1 * c1[c];
    }
}

// ---------------- conv1d (K=3, same) + bias + ReLU, f32x2 packed ----------------
// grid (8 co-tiles of 64, 64 b), block 256. Thread: 4 co (2 pairs) x 8 t.
// fuse=1: second conv -> update zhat/zq and emit squared-error partials (no y write).
#define CI_CHUNK 16
__global__ __launch_bounds__(256) void conv_relu_kernel(
    const float* __restrict__ x, const float* __restrict__ wT,
    const float* __restrict__ bias, float* __restrict__ y,
    int fuse, const float* __restrict__ z)
{
    const int b   = blockIdx.y;
    const int co0 = blockIdx.x * 64;
    __shared__ unsigned long long xs2[CI_CHUNK][130];   // x duplicated in both halves
    __shared__ unsigned long long ws2[CI_CHUNK * 3][32]; // co-adjacent weight pairs
    __shared__ float shred[8];

    const int tid = threadIdx.x;
    const int cg = tid >> 4;   // 0..15 -> co group of 4
    const int tg = tid & 15;   // t = tg + 16u

    unsigned long long acc[2][8];
#pragma unroll
    for (int p = 0; p < 2; p++)
#pragma unroll
        for (int u = 0; u < 8; u++) acc[p][u] = 0ULL;

    for (int ci0 = 0; ci0 < NC; ci0 += CI_CHUNK) {
        for (int e = tid; e < CI_CHUNK * 130; e += 256) {
            int ci = e / 130, tt = e - ci * 130;
            int t = tt - 1;
            float v = 0.0f;
            if ((unsigned)t < (unsigned)NT)
                v = x[((long long)(b * NC + ci0 + ci)) * NT + t];
            xs2[ci][tt] = dup2(v);
        }
        for (int e = tid; e < CI_CHUNK * 3 * 32; e += 256) {
            int k3 = e >> 5, cp = e & 31;
            ws2[k3][cp] = *(const unsigned long long*)
                &wT[((long long)(ci0 * 3 + k3)) * 512 + co0 + cp * 2];
        }
        __syncthreads();
#pragma unroll 4
        for (int ci = 0; ci < CI_CHUNK; ci++) {
            unsigned long long w2[3][2];
#pragma unroll
            for (int k = 0; k < 3; k++)
#pragma unroll
                for (int p = 0; p < 2; p++)
                    w2[k][p] = ws2[ci * 3 + k][cg * 2 + p];
#pragma unroll
            for (int u = 0; u < 8; u++) {
                int t = tg + 16 * u;
                unsigned long long d0 = xs2[ci][t];
                unsigned long long d1 = xs2[ci][t + 1];
                unsigned long long d2 = xs2[ci][t + 2];
#pragma unroll
                for (int p = 0; p < 2; p++) {
                    fma2(acc[p][u], w2[0][p], d0);
                    fma2(acc[p][u], w2[1][p], d1);
                    fma2(acc[p][u], w2[2][p], d2);
                }
            }
        }
        __syncthreads();
    }

    float lsum = 0.0f;
#pragma unroll
    for (int p = 0; p < 2; p++) {
        int co = co0 + cg * 4 + 2 * p;
        float2 bv = *(const float2*)&bias[co];
#pragma unroll
        for (int u = 0; u < 8; u++) {
            int t = tg + 16 * u;
            float2 v = unpack2(acc[p][u]);
            v.x = fmaxf(v.x + bv.x, 0.0f);
            v.y = fmaxf(v.y + bv.y, 0.0f);
            long long i0 = ((long long)(b * NC + co)) * NT + t;
            if (!fuse) {
                y[i0] = v.x;
                y[i0 + NT] = v.y;
            } else {
                float zh0 = g_zhat[i0] + v.x;
                float zh1 = g_zhat[i0 + NT] + v.y;
                g_zhat[i0] = zh0;
                g_zhat[i0 + NT] = zh1;
                g_zq[i0] -= v.x;
                g_zq[i0 + NT] -= v.y;
                float d0 = zh0 - z[i0];
                float d1 = zh1 - z[i0 + NT];
                lsum += d0 * d0 + d1 * d1;
            }
        }
    }
    if (fuse) {
        for (int o = 16; o > 0; o >>= 1) lsum += __shfl_down_sync(0xffffffffu, lsum, o);
        if ((tid & 31) == 0) shred[tid >> 5] = lsum;
        __syncthreads();
        if (tid == 0) {
            float s = 0.0f;
#pragma unroll
            for (int w = 0; w < 8; w++) s += shred[w];
            g_partial[blockIdx.y * 8 + blockIdx.x] = s;
        }
    }
}

// ---------------- per-scale finalize ----------------
__global__ void finalize_kernel(int s) {
    __shared__ float sh[32];
    int tid = threadIdx.x;

    float lsum = (tid < 512) ? g_partial[tid] : 0.0f;
    for (int o = 16; o > 0; o >>= 1) lsum += __shfl_down_sync(0xffffffffu, lsum, o);
    if ((tid & 31) == 0) sh[tid >> 5] = lsum;
    __syncthreads();
    float loss_total = 0.0f;
    if (tid == 0) { for (int w = 0; w < 32; w++) loss_total += sh[w]; }
    __syncthreads();

    int c = g_counts[tid];
    float used = (c > 0) ? 1.0f : 0.0f;
    float p = (float)c / (float)(NB * s);
    float ent = p * logf(p + 1e-10f);

    float us = used;
    for (int o = 16; o > 0; o >>= 1) us += __shfl_down_sync(0xffffffffu, us, o);
    if ((tid & 31) == 0) sh[tid >> 5] = us;
    __syncthreads();
    float used_total = 0.0f;
    if (tid == 0) { for (int w = 0; w < 32; w++) used_total += sh[w]; }
    __syncthreads();

    float es = ent;
    for (int o = 16; o > 0; o >>= 1) es += __shfl_down_sync(0xffffffffu, es, o);
    if ((tid & 31) == 0) sh[tid >> 5] = es;
    __syncthreads();
    float ent_total = 0.0f;
    if (tid == 0) { for (int w = 0; w < 32; w++) ent_total += sh[w]; }

    if (tid == 0) {
        g_sums[0] += used_total * (100.0f / (float)NV);
        g_sums[1] += 1.25f * loss_total / (float)NELEM;
        g_sums[2] += expf(-ent_total);
    }
    g_counts[tid] = 0;
    for (int i = tid; i < NB * NT; i += 1024) g_bestkey[i] = ~0ULL;
}

// ---------------- write outputs ----------------
__global__ void writeout_kernel(float* __restrict__ out, int out_size) {
    long long stride = (long long)gridDim.x * blockDim.x;
    long long t0 = (long long)blockIdx.x * blockDim.x + threadIdx.x;
    for (long long i = t0; i < NELEM && i < out_size; i += stride)
        out[i] = g_zhat[i];
    if (t0 == 0) {
        if (NELEM + 0 < out_size) out[NELEM + 0] = g_sums[0] / 8.0f;
        if (NELEM + 1 < out_size) out[NELEM + 1] = g_sums[1] / 8.0f;
        if (NELEM + 2 < out_size) out[NELEM + 2] = g_sums[2] / 8.0f;
    }
    if (t0 < NB * NIDX && NELEM + 3 + t0 < out_size)
        out[NELEM + 3 + t0] = (float)g_idxbuf[t0];
}

// ---------------- host launch sequence ----------------
extern "C" void kernel_launch(void* const* d_in, const int* in_sizes, int n_in,
                              void* d_out, int out_size) {
    const float* z  = (const float*)d_in[0];
    const float* cb = (const float*)d_in[1];
    const float* pw = (const float*)d_in[2];
    const float* pb = (const float*)d_in[3];
    float* out = (float*)d_out;

    void *p_up = 0, *p_h = 0, *p_wT = 0;
    cudaGetSymbolAddress(&p_up, g_up);
    cudaGetSymbolAddress(&p_h,  g_h);
    cudaGetSymbolAddress(&p_wT, g_wT);

    init_kernel<<<2048, 256>>>(z);
    wtrans_kernel<<<dim3(48, 16, 16), dim3(32, 8)>>>(pw);
    cnorm_kernel<<<NQ * NV, 128>>>(cb);

    for (int q = 0; q < NQ; q++) {
        int s = 1 << q;
        int slog = q;
        int M = NB * s;
        const float* cbq = cb + (long long)q * NV * NC;

        downsample_kernel<<<(NB * NC * s + 255) / 256, 256>>>(s, slog);

        if (s == 1)      quantize_small_kernel<1><<<dim3(64, 8), 256>>>(cbq, q);
        else if (s == 2) quantize_small_kernel<2><<<dim3(64, 8), 256>>>(cbq, q);
        else if (s == 4) quantize_small_kernel<4><<<dim3(64, 8), 256>>>(cbq, q);
        else if (s == 8) quantize_small_kernel<8><<<dim3(64, 8), 256>>>(cbq, q);
        else             quantize_gemm_kernel<<<dim3(M / 64, 8), 256>>>(cbq, q, s, slog);

        post_quantize_kernel<<<(M + 255) / 256, 256>>>(s, slog);
        upsample_kernel<<<dim3(NB, NT), 128>>>(cbq, s);

        const float* wT0 = (const float*)p_wT + ((long long)q * 2 + 0) * 1536 * 512;
        const float* wT1 = (const float*)p_wT + ((long long)q * 2 + 1) * 1536 * 512;
        const float* b0 = pb + ((long long)q * 2 + 0) * NC;
        const float* b1 = pb + ((long long)q * 2 + 1) * NC;
        conv_relu_kernel<<<dim3(8, NB), 256>>>((const float*)p_up, wT0, b0, (float*)p_h, 0, z);
        conv_relu_kernel<<<dim3(8, NB), 256>>>((const float*)p_h,  wT1, b1, (float*)0,   1, z);

        finalize_kernel<<<1, 1024>>>(s);
    }

    writeout_kernel<<<2048, 256>>>(out, out_size);
}

// round 3
// speedup vs baseline: 1.0871x; 1.0022x over previous
#include <cuda_runtime.h>
#include <math.h>

// ---------------- problem constants ----------------
#define NB   64          // batch
#define NC   512         // channels
#define NT   128         // time
#define NV   1024        // codebook entries
#define NQ   8           // scales
#define NIDX 255         // sum of scales
#define NELEM (NB*NC*NT) // 4194304

// ---------------- device scratch ----------------
__device__ float g_zq[NELEM];
__device__ float g_zhat[NELEM];
__device__ float g_xd[NB*NC*NT];
__device__ float g_up[NELEM];
__device__ float g_h[NELEM];
__device__ float g_wT[16ll*1536*512];      // transposed conv weights [q*2+d][ci*3+k][co]
__device__ float g_cnorm[NQ*NV];
__device__ unsigned long long g_bestkey[NB*NT];
__device__ int   g_idxbuf[NB*NIDX];
__device__ int   g_counts[NV];
__device__ float g_partial[512];
__device__ float g_sums[3];

// ---------------- f32x2 helpers ----------------
__device__ __forceinline__ unsigned long long dup2(float x) {
    unsigned long long r;
    asm("mov.b64 %0, {%1, %1};" : "=l"(r) : "f"(x));
    return r;
}
__device__ __forceinline__ void fma2(unsigned long long& a, unsigned long long x, unsigned long long y) {
    asm("fma.rn.f32x2 %0, %1, %2, %0;" : "+l"(a) : "l"(x), "l"(y));
}
__device__ __forceinline__ float2 unpack2(unsigned long long v) {
    float2 f;
    asm("mov.b64 {%0, %1}, %2;" : "=f"(f.x), "=f"(f.y) : "l"(v));
    return f;
}

// ---------------- init ----------------
__global__ void init_kernel(const float* __restrict__ z) {
    long long stride = (long long)gridDim.x * blockDim.x;
    long long t0 = (long long)blockIdx.x * blockDim.x + threadIdx.x;
    for (long long i = t0; i < NELEM; i += stride) {
        g_zq[i] = z[i];
        g_zhat[i] = 0.0f;
    }
    if (t0 < 3)  g_sums[t0] = 0.0f;
    if (t0 < NV) g_counts[t0] = 0;
    if (t0 < NB*NT) g_bestkey[t0] = ~0ULL;
}

// ---------------- weight transpose: w[qd][co][ci3] -> g_wT[qd][ci3][co] ----------------
__global__ void wtrans_kernel(const float* __restrict__ w) {
    __shared__ float tile[32][33];
    int qd  = blockIdx.z;
    int ci0 = blockIdx.x * 32;
    int co0 = blockIdx.y * 32;
    const float* src = w + (long long)qd * 512 * 1536;
    for (int r = threadIdx.y; r < 32; r += 8)
        tile[r][threadIdx.x] = src[(long long)(co0 + r) * 1536 + ci0 + threadIdx.x];
    __syncthreads();
    float* dst = g_wT + (long long)qd * 1536 * 512;
    for (int r = threadIdx.y; r < 32; r += 8)
        dst[(long long)(ci0 + r) * 512 + co0 + threadIdx.x] = tile[threadIdx.x][r];
}

// ---------------- codebook norms ----------------
__global__ void cnorm_kernel(const float* __restrict__ cb) {
    int row = blockIdx.x;
    const float* p = cb + (long long)row * NC;
    float s = 0.0f;
    for (int c = threadIdx.x; c < NC; c += 128) {
        float x = p[c];
        s += x * x;
    }
    __shared__ float sh[4];
    for (int o = 16; o > 0; o >>= 1) s += __shfl_down_sync(0xffffffffu, s, o);
    if ((threadIdx.x & 31) == 0) sh[threadIdx.x >> 5] = s;
    __syncthreads();
    if (threadIdx.x == 0)
        g_cnorm[row] = sh[0] + sh[1] + sh[2] + sh[3];
}

// ---------------- downsample ----------------
__global__ void downsample_kernel(int s, int slog) {
    int total = NB * NC * s;
    int r = NT >> slog;
    int i = blockIdx.x * blockDim.x + threadIdx.x;
    if (i >= total) return;
    int j  = i & (s - 1);
    int bc = i >> slog;
    const float* src = g_zq + (long long)bc * NT + j * r;
    float acc = 0.0f;
    for (int k = 0; k < r; k++) acc += src[k];
    g_xd[i] = acc * (1.0f / (float)r);
}

// ---------------- quantize (small s): grid (64, 8), block 256 ----------------
// Block (b, code-chunk of 128). Each warp: 16 codes. Lane handles dims d = lane + 32e.
template<int S>
__global__ __launch_bounds__(256) void quantize_small_kernel(const float* __restrict__ cb, int q) {
    __shared__ float xs[S][512];
    int b  = blockIdx.x;
    int c0 = blockIdx.y * 128;
    int tid = threadIdx.x;

    for (int e = tid; e < S * 512; e += 256) {
        int j = e >> 9, ch = e & 511;
        xs[j][ch] = g_xd[(b * 512 + ch) * S + j];
    }
    __syncthreads();

    int w = tid >> 5, lane = tid & 31;
    float bestv[S];
    int   besti[S];
#pragma unroll
    for (int j = 0; j < S; j++) { bestv[j] = INFINITY; besti[j] = 0; }

    for (int cc = 0; cc < 16; cc++) {
        int code = c0 + w * 16 + cc;
        const float* cbr = cb + (long long)code * 512;
        float cv[16];
#pragma unroll
        for (int e = 0; e < 16; e++) cv[e] = cbr[lane + 32 * e];
        float cn = g_cnorm[q * NV + code];
#pragma unroll
        for (int j = 0; j < S; j++) {
            float d = 0.0f;
#pragma unroll
            for (int e = 0; e < 16; e++) d += xs[j][lane + 32 * e] * cv[e];
            for (int o = 16; o > 0; o >>= 1) d += __shfl_xor_sync(0xffffffffu, d, o);
            float sc = cn - 2.0f * d;
            if (sc < bestv[j]) { bestv[j] = sc; besti[j] = code; }
        }
    }
    if (lane == 0) {
#pragma unroll
        for (int j = 0; j < S; j++) {
            unsigned u = __float_as_uint(bestv[j]);
            u = (u & 0x80000000u) ? ~u : (u | 0x80000000u);
            unsigned long long key = ((unsigned long long)u << 32) | (unsigned)besti[j];
            atomicMin(&g_bestkey[b * S + j], key);
        }
    }
}

// ---------------- quantize (large s): 64m x 128n tile GEMM w/ f32x2 + fused argmin ----------------
// grid (M/64, 8), block 256. Thread: m = ti+16r (r<4), n pairs (2tj+32c, +1) (c<4).
__global__ __launch_bounds__(256) void quantize_gemm_kernel(
    const float* __restrict__ cb, int q, int s, int slog)
{
    const int m0 = blockIdx.x * 64;
    const int n0 = blockIdx.y * 128;
    __shared__ float As[32][65];
    __shared__ float Bs[32][130];

    const int tid = threadIdx.x;
    const int ti = tid >> 4;   // 0..15
    const int tj = tid & 15;   // 0..15

    unsigned long long acc[4][4];
#pragma unroll
    for (int r = 0; r < 4; r++)
#pragma unroll
        for (int c = 0; c < 4; c++) acc[r][c] = 0ULL;

    for (int kc = 0; kc < NC; kc += 32) {
#pragma unroll
        for (int it = 0; it < 8; it++) {
            int e = tid + 256 * it;   // e < 2048
            int m = e & 63, kk = e >> 6;
            int gm = m0 + m;
            int b = gm >> slog;
            int j = gm & (s - 1);
            As[kk][m] = g_xd[(((long long)b * NC + (kc + kk)) << slog) + j];
        }
#pragma unroll
        for (int it = 0; it < 16; it++) {
            int e = tid + 256 * it;   // e < 4096
            int kk = e & 31, n = e >> 5;
            Bs[kk][n] = cb[(long long)(n0 + n) * NC + kc + kk];
        }
        __syncthreads();
#pragma unroll 8
        for (int kk = 0; kk < 32; kk++) {
            unsigned long long a2[4], b2[4];
#pragma unroll
            for (int r = 0; r < 4; r++) a2[r] = dup2(As[kk][ti + 16 * r]);
#pragma unroll
            for (int c = 0; c < 4; c++)
                b2[c] = *(const unsigned long long*)&Bs[kk][2 * tj + 32 * c];
#pragma unroll
            for (int r = 0; r < 4; r++)
#pragma unroll
                for (int c = 0; c < 4; c++)
                    fma2(acc[r][c], a2[r], b2[c]);
        }
        __syncthreads();
    }

    float bestv[4];
    int   besti[4];
#pragma unroll
    for (int r = 0; r < 4; r++) { bestv[r] = INFINITY; besti[r] = 0; }
#pragma unroll
    for (int c = 0; c < 4; c++) {
        int n = n0 + 2 * tj + 32 * c;
        float cn0 = g_cnorm[q * NV + n];
        float cn1 = g_cnorm[q * NV + n + 1];
#pragma unroll
        for (int r = 0; r < 4; r++) {
            float2 dv = unpack2(acc[r][c]);
            float s0 = cn0 - 2.0f * dv.x;
            float s1 = cn1 - 2.0f * dv.y;
            if (s0 < bestv[r]) { bestv[r] = s0; besti[r] = n; }
            if (s1 < bestv[r]) { bestv[r] = s1; besti[r] = n + 1; }
        }
    }
#pragma unroll
    for (int r = 0; r < 4; r++) {
        float v = bestv[r];
        int   ix = besti[r];
        for (int off = 8; off > 0; off >>= 1) {
            float ov = __shfl_down_sync(0xffffffffu, v, off, 16);
            int   oi = __shfl_down_sync(0xffffffffu, ix, off, 16);
            if (ov < v || (ov == v && oi < ix)) { v = ov; ix = oi; }
        }
        if (tj == 0) {
            int gm = m0 + ti + 16 * r;
            unsigned u = __float_as_uint(v);
            u = (u & 0x80000000u) ? ~u : (u | 0x80000000u);
            unsigned long long key = ((unsigned long long)u << 32) | (unsigned)ix;
            atomicMin(&g_bestkey[gm], key);
        }
    }
}

// ---------------- extract idx, histogram ----------------
__global__ void post_quantize_kernel(int s, int slog) {
    int m = blockIdx.x * blockDim.x + threadIdx.x;
    int M = NB * s;
    if (m >= M) return;
    int v = (int)(g_bestkey[m] & 0xFFFFFFFFULL);
    int b = m >> slog;
    int j = m & (s - 1);
    g_idxbuf[b * NIDX + (s - 1) + j] = v;
    atomicAdd(&g_counts[v], 1);
}

// ---------------- gather + linear upsample ----------------
__global__ void upsample_kernel(const float* __restrict__ cb, int s) {
    int b = blockIdx.x;
    int t = blockIdx.y;
    float u = (t + 0.5f) * ((float)s / 128.0f) - 0.5f;
    float jf = floorf(u);
    float f = u - jf;
    int j0 = (int)jf;
    int j1 = j0 + 1;
    if (j0 < 0) j0 = 0; if (j0 > s - 1) j0 = s - 1;
    if (j1 < 0) j1 = 0; if (j1 > s - 1) j1 = s - 1;
    int v0 = g_idxbuf[b * NIDX + (s - 1) + j0];
    int v1 = g_idxbuf[b * NIDX + (s - 1) + j1];
    const float* c0 = cb + (long long)v0 * NC;
    const float* c1 = cb + (long long)v1 * NC;
    float w1 = f, w0 = 1.0f - f;
    for (int c = threadIdx.x; c < NC; c += 128) {
        g_up[((long long)b * NC + c) * NT + t] = w0 * c0[c] + w1 * c1[c];
    }
}

// ---------------- conv1d (K=3, same) + bias + ReLU, f32x2 packed ----------------
// grid (8 co-tiles of 64, 64 b), block 256. Thread: 4 co (2 pairs) x 8 t.
// fuse=1: second conv -> update zhat/zq and emit squared-error partials (no y write).
#define CI_CHUNK 16
__global__ __launch_bounds__(256) void conv_relu_kernel(
    const float* __restrict__ x, const float* __restrict__ wT,
    const float* __restrict__ bias, float* __restrict__ y,
    int fuse, const float* __restrict__ z)
{
    const int b   = blockIdx.y;
    const int co0 = blockIdx.x * 64;
    __shared__ unsigned long long xs2[CI_CHUNK][130];   // x duplicated in both halves
    __shared__ unsigned long long ws2[CI_CHUNK * 3][32]; // co-adjacent weight pairs
    __shared__ float shred[8];

    const int tid = threadIdx.x;
    const int cg = tid >> 4;   // 0..15 -> co group of 4
    const int tg = tid & 15;   // t = tg + 16u

    unsigned long long acc[2][8];
#pragma unroll
    for (int p = 0; p < 2; p++)
#pragma unroll
        for (int u = 0; u < 8; u++) acc[p][u] = 0ULL;

    for (int ci0 = 0; ci0 < NC; ci0 += CI_CHUNK) {
        for (int e = tid; e < CI_CHUNK * 130; e += 256) {
            int ci = e / 130, tt = e - ci * 130;
            int t = tt - 1;
            float v = 0.0f;
            if ((unsigned)t < (unsigned)NT)
                v = x[((long long)(b * NC + ci0 + ci)) * NT + t];
            xs2[ci][tt] = dup2(v);
        }
        for (int e = tid; e < CI_CHUNK * 3 * 32; e += 256) {
            int k3 = e >> 5, cp = e & 31;
            ws2[k3][cp] = *(const unsigned long long*)
                &wT[((long long)(ci0 * 3 + k3)) * 512 + co0 + cp * 2];
        }
        __syncthreads();
#pragma unroll 4
        for (int ci = 0; ci < CI_CHUNK; ci++) {
            unsigned long long w2[3][2];
#pragma unroll
            for (int k = 0; k < 3; k++)
#pragma unroll
                for (int p = 0; p < 2; p++)
                    w2[k][p] = ws2[ci * 3 + k][cg * 2 + p];
#pragma unroll
            for (int u = 0; u < 8; u++) {
                int t = tg + 16 * u;
                unsigned long long d0 = xs2[ci][t];
                unsigned long long d1 = xs2[ci][t + 1];
                unsigned long long d2 = xs2[ci][t + 2];
#pragma unroll
                for (int p = 0; p < 2; p++) {
                    fma2(acc[p][u], w2[0][p], d0);
                    fma2(acc[p][u], w2[1][p], d1);
                    fma2(acc[p][u], w2[2][p], d2);
                }
            }
        }
        __syncthreads();
    }

    float lsum = 0.0f;
#pragma unroll
    for (int p = 0; p < 2; p++) {
        int co = co0 + cg * 4 + 2 * p;
        float2 bv = *(const float2*)&bias[co];
#pragma unroll
        for (int u = 0; u < 8; u++) {
            int t = tg + 16 * u;
            float2 v = unpack2(acc[p][u]);
            v.x = fmaxf(v.x + bv.x, 0.0f);
            v.y = fmaxf(v.y + bv.y, 0.0f);
            long long i0 = ((long long)(b * NC + co)) * NT + t;
            if (!fuse) {
                y[i0] = v.x;
                y[i0 + NT] = v.y;
            } else {
                float zh0 = g_zhat[i0] + v.x;
                float zh1 = g_zhat[i0 + NT] + v.y;
                g_zhat[i0] = zh0;
                g_zhat[i0 + NT] = zh1;
                g_zq[i0] -= v.x;
                g_zq[i0 + NT] -= v.y;
                float d0 = zh0 - z[i0];
                float d1 = zh1 - z[i0 + NT];
                lsum += d0 * d0 + d1 * d1;
            }
        }
    }
    if (fuse) {
        for (int o = 16; o > 0; o >>= 1) lsum += __shfl_down_sync(0xffffffffu, lsum, o);
        if ((tid & 31) == 0) shred[tid >> 5] = lsum;
        __syncthreads();
        if (tid == 0) {
            float s = 0.0f;
#pragma unroll
            for (int w = 0; w < 8; w++) s += shred[w];
            g_partial[blockIdx.y * 8 + blockIdx.x] = s;
        }
    }
}

// ---------------- per-scale finalize ----------------
__global__ void finalize_kernel(int s) {
    __shared__ float sh[32];
    int tid = threadIdx.x;

    float lsum = (tid < 512) ? g_partial[tid] : 0.0f;
    for (int o = 16; o > 0; o >>= 1) lsum += __shfl_down_sync(0xffffffffu, lsum, o);
    if ((tid & 31) == 0) sh[tid >> 5] = lsum;
    __syncthreads();
    float loss_total = 0.0f;
    if (tid == 0) { for (int w = 0; w < 32; w++) loss_total += sh[w]; }
    __syncthreads();

    int c = g_counts[tid];
    float used = (c > 0) ? 1.0f : 0.0f;
    float p = (float)c / (float)(NB * s);
    float ent = p * logf(p + 1e-10f);

    float us = used;
    for (int o = 16; o > 0; o >>= 1) us += __shfl_down_sync(0xffffffffu, us, o);
    if ((tid & 31) == 0) sh[tid >> 5] = us;
    __syncthreads();
    float used_total = 0.0f;
    if (tid == 0) { for (int w = 0; w < 32; w++) used_total += sh[w]; }
    __syncthreads();

    float es = ent;
    for (int o = 16; o > 0; o >>= 1) es += __shfl_down_sync(0xffffffffu, es, o);
    if ((tid & 31) == 0) sh[tid >> 5] = es;
    __syncthreads();
    float ent_total = 0.0f;
    if (tid == 0) { for (int w = 0; w < 32; w++) ent_total += sh[w]; }

    if (tid == 0) {
        g_sums[0] += used_total * (100.0f / (float)NV);
        g_sums[1] += 1.25f * loss_total / (float)NELEM;
        g_sums[2] += expf(-ent_total);
    }
    g_counts[tid] = 0;
    for (int i = tid; i < NB * NT; i += 1024) g_bestkey[i] = ~0ULL;
}

// ---------------- write outputs ----------------
__global__ void writeout_kernel(float* __restrict__ out, int out_size) {
    long long stride = (long long)gridDim.x * blockDim.x;
    long long t0 = (long long)blockIdx.x * blockDim.x + threadIdx.x;
    for (long long i = t0; i < NELEM && i < out_size; i += stride)
        out[i] = g_zhat[i];
    if (t0 == 0) {
        if (NELEM + 0 < out_size) out[NELEM + 0] = g_sums[0] / 8.0f;
        if (NELEM + 1 < out_size) out[NELEM + 1] = g_sums[1] / 8.0f;
        if (NELEM + 2 < out_size) out[NELEM + 2] = g_sums[2] / 8.0f;
    }
    if (t0 < NB * NIDX && NELEM + 3 + t0 < out_size)
        out[NELEM + 3 + t0] = (float)g_idxbuf[t0];
}

// ---------------- host launch sequence ----------------
extern "C" void kernel_launch(void* const* d_in, const int* in_sizes, int n_in,
                              void* d_out, int out_size) {
    const float* z  = (const float*)d_in[0];
    const float* cb = (const float*)d_in[1];
    const float* pw = (const float*)d_in[2];
    const float* pb = (const float*)d_in[3];
    float* out = (float*)d_out;

    void *p_up = 0, *p_h = 0, *p_wT = 0;
    cudaGetSymbolAddress(&p_up, g_up);
    cudaGetSymbolAddress(&p_h,  g_h);
    cudaGetSymbolAddress(&p_wT, g_wT);

    init_kernel<<<2048, 256>>>(z);
    wtrans_kernel<<<dim3(48, 16, 16), dim3(32, 8)>>>(pw);
    cnorm_kernel<<<NQ * NV, 128>>>(cb);

    for (int q = 0; q < NQ; q++) {
        int s = 1 << q;
        int slog = q;
        int M = NB * s;
        const float* cbq = cb + (long long)q * NV * NC;

        downsample_kernel<<<(NB * NC * s + 255) / 256, 256>>>(s, slog);

        if (s == 1)      quantize_small_kernel<1><<<dim3(64, 8), 256>>>(cbq, q);
        else if (s == 2) quantize_small_kernel<2><<<dim3(64, 8), 256>>>(cbq, q);
        else if (s == 4) quantize_small_kernel<4><<<dim3(64, 8), 256>>>(cbq, q);
        else if (s == 8) quantize_small_kernel<8><<<dim3(64, 8), 256>>>(cbq, q);
        else             quantize_gemm_kernel<<<dim3(M / 64, 8), 256>>>(cbq, q, s, slog);

        post_quantize_kernel<<<(M + 255) / 256, 256>>>(s, slog);
        upsample_kernel<<<dim3(NB, NT), 128>>>(cbq, s);

        const float* wT0 = (const float*)p_wT + ((long long)q * 2 + 0) * 1536 * 512;
        const float* wT1 = (const float*)p_wT + ((long long)q * 2 + 1) * 1536 * 512;
        const float* b0 = pb + ((long long)q * 2 + 0) * NC;
        const float* b1 = pb + ((long long)q * 2 + 1) * NC;
        conv_relu_kernel<<<dim3(8, NB), 256>>>((const float*)p_up, wT0, b0, (float*)p_h, 0, z);
        conv_relu_kernel<<<dim3(8, NB), 256>>>((const float*)p_h,  wT1, b1, (float*)0,   1, z);

        finalize_kernel<<<1, 1024>>>(s);
    }

    writeout_kernel<<<2048, 256>>>(out, out_size);
}

// round 5
// speedup vs baseline: 1.3172x; 1.2117x over previous
#include <cuda_runtime.h>
#include <math.h>

#define NB   64
#define NC   512
#define NT   128
#define NV   1024
#define NQ   8
#define NIDX 255
#define NELEM (NB*NC*NT)
#define PLANE ((long long)NB*NT*NC)

// ---------------- device scratch ----------------
__device__ float g_zq[NELEM];
__device__ float g_zhat[NELEM];
__device__ float g_xd[NB*NC*NT];
__device__ float g_xs_a[2ll*NB*NT*NC];   // conv1 input tf32 splits [2][b][t][ci]
__device__ float g_xs_b[2ll*NB*NT*NC];   // conv2 input tf32 splits
__device__ float g_wsp[16ll*6*NC*NC];    // [qd][split*3+tap][co][ci] tf32 values
__device__ float g_cnorm[NQ*NV];
__device__ unsigned long long g_bestkey[NB*NT];
__device__ int   g_idxbuf[NB*NIDX];
__device__ int   g_counts[NV];
__device__ float g_partial[256];
__device__ float g_sums[3];

// ---------------- tf32 split helpers ----------------
__device__ __forceinline__ float tf32r(float x) {
    unsigned u;
    asm("cvt.rna.tf32.f32 %0, %1;" : "=r"(u) : "f"(x));
    return __uint_as_float(u);
}
__device__ __forceinline__ void split2(float x, float& hi, float& lo) {
    hi = tf32r(x);
    lo = tf32r(x - hi);
}

// ---------------- f32x2 helpers (quantize gemm) ----------------
__device__ __forceinline__ unsigned long long dup2(float x) {
    unsigned long long r;
    asm("mov.b64 %0, {%1, %1};" : "=l"(r) : "f"(x));
    return r;
}
__device__ __forceinline__ void fma2(unsigned long long& a, unsigned long long x, unsigned long long y) {
    asm("fma.rn.f32x2 %0, %1, %2, %0;" : "+l"(a) : "l"(x), "l"(y));
}
__device__ __forceinline__ float2 unpack2(unsigned long long v) {
    float2 f;
    asm("mov.b64 {%0, %1}, %2;" : "=f"(f.x), "=f"(f.y) : "l"(v));
    return f;
}

// ---------------- init ----------------
__global__ void init_kernel(const float* __restrict__ z) {
    long long stride = (long long)gridDim.x * blockDim.x;
    long long t0 = (long long)blockIdx.x * blockDim.x + threadIdx.x;
    for (long long i = t0; i < NELEM; i += stride) { g_zq[i] = z[i]; g_zhat[i] = 0.0f; }
    if (t0 < 3)  g_sums[t0] = 0.0f;
    if (t0 < NV) g_counts[t0] = 0;
    if (t0 < NB*NT) g_bestkey[t0] = ~0ULL;
}

// ---------------- weight split: pw[qd][co][ci][k] -> g_wsp[qd][split*3+k][co][ci] ----------------
__global__ void wsplit_kernel(const float* __restrict__ pw) {
    long long i = (long long)blockIdx.x * 256 + threadIdx.x;
    if (i >= 16ll * NC * NC) return;
    int qd = (int)(i >> 18);
    int r  = (int)(i & (NC*NC - 1));
    int co = r >> 9, ci = r & 511;
    const float* src = pw + (((long long)qd * NC + co) * NC + ci) * 3;
    float* dst = g_wsp + (long long)qd * 6 * NC * NC;
#pragma unroll
    for (int k = 0; k < 3; k++) {
        float hi, lo;
        split2(src[k], hi, lo);
        dst[(long long)k * NC * NC + co * NC + ci]       = hi;
        dst[(long long)(3 + k) * NC * NC + co * NC + ci] = lo;
    }
}

// ---------------- codebook norms ----------------
__global__ void cnorm_kernel(const float* __restrict__ cb) {
    int row = blockIdx.x;
    const float* p = cb + (long long)row * NC;
    float s = 0.0f;
    for (int c = threadIdx.x; c < NC; c += 128) { float x = p[c]; s += x * x; }
    __shared__ float sh[4];
    for (int o = 16; o > 0; o >>= 1) s += __shfl_down_sync(0xffffffffu, s, o);
    if ((threadIdx.x & 31) == 0) sh[threadIdx.x >> 5] = s;
    __syncthreads();
    if (threadIdx.x == 0) g_cnorm[row] = sh[0] + sh[1] + sh[2] + sh[3];
}

// ---------------- downsample ----------------
__global__ void downsample_kernel(int s, int slog) {
    int total = NB * NC * s;
    int r = NT >> slog;
    int i = blockIdx.x * blockDim.x + threadIdx.x;
    if (i >= total) return;
    int j  = i & (s - 1);
    int bc = i >> slog;
    const float* src = g_zq + (long long)bc * NT + j * r;
    float acc = 0.0f;
    for (int k = 0; k < r; k++) acc += src[k];
    g_xd[i] = acc * (1.0f / (float)r);
}

// ---------------- quantize (s<=8) ----------------
template<int S>
__global__ __launch_bounds__(256) void quantize_small_kernel(const float* __restrict__ cb, int q) {
    __shared__ float xs[S][512];
    int b  = blockIdx.x;
    int c0 = blockIdx.y * 128;
    int tid = threadIdx.x;
    for (int e = tid; e < S * 512; e += 256) {
        int j = e >> 9, ch = e & 511;
        xs[j][ch] = g_xd[(b * 512 + ch) * S + j];
    }
    __syncthreads();
    int w = tid >> 5, lane = tid & 31;
    float bestv[S]; int besti[S];
#pragma unroll
    for (int j = 0; j < S; j++) { bestv[j] = INFINITY; besti[j] = 0; }
    for (int cc = 0; cc < 16; cc++) {
        int code = c0 + w * 16 + cc;
        const float* cbr = cb + (long long)code * 512;
        float cv[16];
#pragma unroll
        for (int e = 0; e < 16; e++) cv[e] = cbr[lane + 32 * e];
        float cn = g_cnorm[q * NV + code];
#pragma unroll
        for (int j = 0; j < S; j++) {
            float d = 0.0f;
#pragma unroll
            for (int e = 0; e < 16; e++) d += xs[j][lane + 32 * e] * cv[e];
            for (int o = 16; o > 0; o >>= 1) d += __shfl_xor_sync(0xffffffffu, d, o);
            float sc = cn - 2.0f * d;
            if (sc < bestv[j]) { bestv[j] = sc; besti[j] = code; }
        }
    }
    if (lane == 0) {
#pragma unroll
        for (int j = 0; j < S; j++) {
            unsigned u = __float_as_uint(bestv[j]);
            u = (u & 0x80000000u) ? ~u : (u | 0x80000000u);
            atomicMin(&g_bestkey[b * S + j], ((unsigned long long)u << 32) | (unsigned)besti[j]);
        }
    }
}

// ---------------- quantize (s>=16) ----------------
__global__ __launch_bounds__(256) void quantize_gemm_kernel(
    const float* __restrict__ cb, int q, int s, int slog)
{
    const int m0 = blockIdx.x * 64;
    const int n0 = blockIdx.y * 128;
    __shared__ float As[32][65];
    __shared__ float Bs[32][130];
    const int tid = threadIdx.x;
    const int ti = tid >> 4, tj = tid & 15;
    unsigned long long acc[4][4];
#pragma unroll
    for (int r = 0; r < 4; r++)
#pragma unroll
        for (int c = 0; c < 4; c++) acc[r][c] = 0ULL;
    for (int kc = 0; kc < NC; kc += 32) {
#pragma unroll
        for (int it = 0; it < 8; it++) {
            int e = tid + 256 * it;
            int m = e & 63, kk = e >> 6;
            int gm = m0 + m;
            int b = gm >> slog, j = gm & (s - 1);
            As[kk][m] = g_xd[(((long long)b * NC + (kc + kk)) << slog) + j];
        }
#pragma unroll
        for (int it = 0; it < 16; it++) {
            int e = tid + 256 * it;
            int kk = e & 31, n = e >> 5;
            Bs[kk][n] = cb[(long long)(n0 + n) * NC + kc + kk];
        }
        __syncthreads();
#pragma unroll 8
        for (int kk = 0; kk < 32; kk++) {
            unsigned long long a2[4], b2[4];
#pragma unroll
            for (int r = 0; r < 4; r++) a2[r] = dup2(As[kk][ti + 16 * r]);
#pragma unroll
            for (int c = 0; c < 4; c++) b2[c] = *(const unsigned long long*)&Bs[kk][2 * tj + 32 * c];
#pragma unroll
            for (int r = 0; r < 4; r++)
#pragma unroll
                for (int c = 0; c < 4; c++) fma2(acc[r][c], a2[r], b2[c]);
        }
        __syncthreads();
    }
    float bestv[4]; int besti[4];
#pragma unroll
    for (int r = 0; r < 4; r++) { bestv[r] = INFINITY; besti[r] = 0; }
#pragma unroll
    for (int c = 0; c < 4; c++) {
        int n = n0 + 2 * tj + 32 * c;
        float cn0 = g_cnorm[q * NV + n], cn1 = g_cnorm[q * NV + n + 1];
#pragma unroll
        for (int r = 0; r < 4; r++) {
            float2 dv = unpack2(acc[r][c]);
            float s0 = cn0 - 2.0f * dv.x, s1 = cn1 - 2.0f * dv.y;
            if (s0 < bestv[r]) { bestv[r] = s0; besti[r] = n; }
            if (s1 < bestv[r]) { bestv[r] = s1; besti[r] = n + 1; }
        }
    }
#pragma unroll
    for (int r = 0; r < 4; r++) {
        float v = bestv[r]; int ix = besti[r];
        for (int off = 8; off > 0; off >>= 1) {
            float ov = __shfl_down_sync(0xffffffffu, v, off, 16);
            int   oi = __shfl_down_sync(0xffffffffu, ix, off, 16);
            if (ov < v || (ov == v && oi < ix)) { v = ov; ix = oi; }
        }
        if (tj == 0) {
            unsigned u = __float_as_uint(v);
            u = (u & 0x80000000u) ? ~u : (u | 0x80000000u);
            atomicMin(&g_bestkey[m0 + ti + 16 * r], ((unsigned long long)u << 32) | (unsigned)ix);
        }
    }
}

// ---------------- extract idx + histogram ----------------
__global__ void post_quantize_kernel(int s, int slog) {
    int m = blockIdx.x * blockDim.x + threadIdx.x;
    if (m >= NB * s) return;
    int v = (int)(g_bestkey[m] & 0xFFFFFFFFULL);
    int b = m >> slog, j = m & (s - 1);
    g_idxbuf[b * NIDX + (s - 1) + j] = v;
    atomicAdd(&g_counts[v], 1);
}

// ---------------- upsample -> tf32 splits [2][b][t][ci] ----------------
__global__ void upsample_split_kernel(const float* __restrict__ cb, int s) {
    int b = blockIdx.x, t = blockIdx.y;
    float u = (t + 0.5f) * ((float)s / 128.0f) - 0.5f;
    float jf = floorf(u);
    float f = u - jf;
    int j0 = (int)jf, j1 = j0 + 1;
    if (j0 < 0) j0 = 0; if (j0 > s - 1) j0 = s - 1;
    if (j1 < 0) j1 = 0; if (j1 > s - 1) j1 = s - 1;
    int v0 = g_idxbuf[b * NIDX + (s - 1) + j0];
    int v1 = g_idxbuf[b * NIDX + (s - 1) + j1];
    const float* c0 = cb + (long long)v0 * NC;
    const float* c1 = cb + (long long)v1 * NC;
    float w1 = f, w0 = 1.0f - f;
    long long base = ((long long)(b * NT + t)) * NC;
    for (int c = threadIdx.x; c < NC; c += 128) {
        float val = w0 * c0[c] + w1 * c1[c];
        float hi, lo;
        split2(val, hi, lo);
        g_xs_a[base + c]         = hi;
        g_xs_a[base + c + PLANE] = lo;
    }
}

// ---------------- tensor-core conv via mma.sync tf32 (sm_100-safe) ----------------
// CTA: (co-tile 128, batch). 256 threads = 8 warps: cg = w/4 (co half of 64), tg = w%4 (t group of 32).
// K loop: 32 ci-chunks of 16. Per chunk: 4 split terms x 3 taps x 2 k8-steps, m16n8k8 mma.
// smem: X[2 splits][130 rows x pitch24] @0/3120 floats; W[6 tiles][128 x pitch24] @6240. Total 24672 floats.
#define CONV_SMEM (24672*4)
__global__ __launch_bounds__(256) void conv_tc_kernel(
    const float* __restrict__ xs,   // [2][b][t][ci]
    const float* __restrict__ wsp,  // [6][co][ci] for this layer
    const float* __restrict__ bias,
    float* __restrict__ ys,         // conv1 out splits (fuse=0)
    const float* __restrict__ z, int fuse)
{
    extern __shared__ float sm[];
    const int tid = threadIdx.x, lane = tid & 31, wp = tid >> 5;
    const int cg = wp >> 2, tg = wp & 3;
    const int b = blockIdx.y, co0 = blockIdx.x * 128;
    const int lq = lane >> 2, lr = lane & 3;

    float acc[4][4][4];
#pragma unroll
    for (int mt = 0; mt < 4; mt++)
#pragma unroll
        for (int nt = 0; nt < 4; nt++)
#pragma unroll
            for (int r = 0; r < 4; r++) acc[mt][nt][r] = 0.0f;

    for (int ch = 0; ch < 32; ch++) {
        int ci0 = ch * 16;
        // ---- load X tiles (2 splits, 130 halo rows x 16 ci) ----
        for (int e = tid; e < 1040; e += 256) {
            int sp = (e >= 520);
            int r = e - sp * 520;
            int row = r >> 2, q = r & 3;
            int t = row - 1;
            float4 v = make_float4(0.f, 0.f, 0.f, 0.f);
            if ((unsigned)t < 128u)
                v = *(const float4*)(xs + sp * PLANE + ((long long)(b * NT + t)) * NC + ci0 + q * 4);
            float* dst = sm + sp * 3120 + row * 24;
            const float* pv = (const float*)&v;
#pragma unroll
            for (int li = 0; li < 4; li++) {
                int lc = q * 4 + li;
                int c = lc & 7;
                dst[((lc >> 3) << 3) + ((c & 3) << 1) + (c >> 2)] = pv[li];
            }
        }
        // ---- load W tiles (6 = split*3+tap, 128 co x 16 ci) ----
        for (int e = tid; e < 3072; e += 256) {
            int tile = e >> 9;
            int r = e & 511;
            int row = r >> 2, q = r & 3;
            float4 v = *(const float4*)(wsp + (long long)tile * (NC * NC)
                                        + (long long)(co0 + row) * NC + ci0 + q * 4);
            float* dst = sm + 6240 + tile * 3072 + row * 24;
            const float* pv = (const float*)&v;
#pragma unroll
            for (int li = 0; li < 4; li++) {
                int lc = q * 4 + li;
                int c = lc & 7;
                dst[((lc >> 3) << 3) + ((c & 3) << 1) + (c >> 2)] = pv[li];
            }
        }
        __syncthreads();
        // ---- mma: terms (wa,xb) in {(0,0),(0,1),(1,0),(1,1)} ----
        for (int term = 0; term < 4; term++) {
            int wa = term >> 1, xb = term & 1;
            for (int tap = 0; tap < 3; tap++) {
                const float* Wt = sm + 6240 + (wa * 3 + tap) * 3072;
                const float* Xt = sm + xb * 3120;
#pragma unroll
                for (int k8 = 0; k8 < 2; k8++) {
                    unsigned a[4][4];
#pragma unroll
                    for (int mt = 0; mt < 4; mt++) {
                        int row = cg * 64 + mt * 16 + lq;
                        uint2 p0 = *(const uint2*)&Wt[row * 24 + k8 * 8 + lr * 2];
                        uint2 p1 = *(const uint2*)&Wt[(row + 8) * 24 + k8 * 8 + lr * 2];
                        a[mt][0] = p0.x; a[mt][2] = p0.y;
                        a[mt][1] = p1.x; a[mt][3] = p1.y;
                    }
#pragma unroll
                    for (int nt = 0; nt < 4; nt++) {
                        int trow = tg * 32 + nt * 8 + lq + tap;
                        uint2 bb = *(const uint2*)&Xt[trow * 24 + k8 * 8 + lr * 2];
#pragma unroll
                        for (int mt = 0; mt < 4; mt++) {
                            asm volatile(
                                "mma.sync.aligned.m16n8k8.row.col.f32.tf32.tf32.f32 "
                                "{%0,%1,%2,%3}, {%4,%5,%6,%7}, {%8,%9}, {%0,%1,%2,%3};"
                                : "+f"(acc[mt][nt][0]), "+f"(acc[mt][nt][1]),
                                  "+f"(acc[mt][nt][2]), "+f"(acc[mt][nt][3])
                                : "r"(a[mt][0]), "r"(a[mt][1]), "r"(a[mt][2]), "r"(a[mt][3]),
                                  "r"(bb.x), "r"(bb.y));
                        }
                    }
                }
            }
        }
        __syncthreads();
    }

    // ---- epilogue ----
    if (!fuse) {
        // transpose via smem [t][co] pitch 130, then coalesced split writes
#pragma unroll
        for (int mt = 0; mt < 4; mt++)
#pragma unroll
            for (int nt = 0; nt < 4; nt++) {
                int row = cg * 64 + mt * 16 + lq;
                int t0 = tg * 32 + nt * 8 + lr * 2;
                sm[t0 * 130 + row]           = acc[mt][nt][0];
                sm[(t0 + 1) * 130 + row]     = acc[mt][nt][1];
                sm[t0 * 130 + row + 8]       = acc[mt][nt][2];
                sm[(t0 + 1) * 130 + row + 8] = acc[mt][nt][3];
            }
        __syncthreads();
        for (int e = tid; e < 16384; e += 256) {
            int t = e >> 7, co = e & 127;
            float v = fmaxf(sm[t * 130 + co] + bias[co0 + co], 0.0f);
            float hi, lo;
            split2(v, hi, lo);
            long long o = ((long long)(b * NT + t)) * NC + co0 + co;
            ys[o]         = hi;
            ys[o + PLANE] = lo;
        }
    } else {
        float lsum = 0.0f;
#pragma unroll
        for (int mt = 0; mt < 4; mt++)
#pragma unroll
            for (int nt = 0; nt < 4; nt++) {
                int row = cg * 64 + mt * 16 + lq;
                int t0 = tg * 32 + nt * 8 + lr * 2;
#pragma unroll
                for (int h = 0; h < 2; h++) {
                    int co = co0 + row + h * 8;
                    float bv = bias[co];
                    float y0 = fmaxf(acc[mt][nt][h * 2 + 0] + bv, 0.0f);
                    float y1 = fmaxf(acc[mt][nt][h * 2 + 1] + bv, 0.0f);
                    long long i = ((long long)(b * NC + co)) * NT + t0;
                    float2 zh  = *(float2*)&g_zhat[i];
                    float2 zz  = *(const float2*)&z[i];
                    float2 zqv = *(float2*)&g_zq[i];
                    zh.x += y0; zh.y += y1;
                    *(float2*)&g_zhat[i] = zh;
                    zqv.x -= y0; zqv.y -= y1;
                    *(float2*)&g_zq[i] = zqv;
                    float d0 = zh.x - zz.x, d1 = zh.y - zz.y;
                    lsum += d0 * d0 + d1 * d1;
                }
            }
        __syncthreads();
        for (int o = 16; o > 0; o >>= 1) lsum += __shfl_down_sync(0xffffffffu, lsum, o);
        if ((tid & 31) == 0) sm[tid >> 5] = lsum;
        __syncthreads();
        if (tid == 0) {
            float s = 0.0f;
#pragma unroll
            for (int i2 = 0; i2 < 8; i2++) s += sm[i2];
            g_partial[blockIdx.y * 4 + blockIdx.x] = s;
        }
    }
}

// ---------------- per-scale finalize ----------------
__global__ void finalize_kernel(int s) {
    __shared__ float sh[32];
    int tid = threadIdx.x;
    float lsum = (tid < 256) ? g_partial[tid] : 0.0f;
    for (int o = 16; o > 0; o >>= 1) lsum += __shfl_down_sync(0xffffffffu, lsum, o);
    if ((tid & 31) == 0) sh[tid >> 5] = lsum;
    __syncthreads();
    float loss_total = 0.0f;
    if (tid == 0) for (int w = 0; w < 32; w++) loss_total += sh[w];
    __syncthreads();
    int c = g_counts[tid];
    float used = (c > 0) ? 1.0f : 0.0f;
    float p = (float)c / (float)(NB * s);
    float ent = p * logf(p + 1e-10f);
    float us = used;
    for (int o = 16; o > 0; o >>= 1) us += __shfl_down_sync(0xffffffffu, us, o);
    if ((tid & 31) == 0) sh[tid >> 5] = us;
    __syncthreads();
    float used_total = 0.0f;
    if (tid == 0) for (int w = 0; w < 32; w++) used_total += sh[w];
    __syncthreads();
    float es = ent;
    for (int o = 16; o > 0; o >>= 1) es += __shfl_down_sync(0xffffffffu, es, o);
    if ((tid & 31) == 0) sh[tid >> 5] = es;
    __syncthreads();
    float ent_total = 0.0f;
    if (tid == 0) for (int w = 0; w < 32; w++) ent_total += sh[w];
    if (tid == 0) {
        g_sums[0] += used_total * (100.0f / (float)NV);
        g_sums[1] += 1.25f * loss_total / (float)NELEM;
        g_sums[2] += expf(-ent_total);
    }
    g_counts[tid] = 0;
    for (int i = tid; i < NB * NT; i += 1024) g_bestkey[i] = ~0ULL;
}

// ---------------- write outputs ----------------
__global__ void writeout_kernel(float* __restrict__ out, int out_size) {
    long long stride = (long long)gridDim.x * blockDim.x;
    long long t0 = (long long)blockIdx.x * blockDim.x + threadIdx.x;
    for (long long i = t0; i < NELEM && i < out_size; i += stride) out[i] = g_zhat[i];
    if (t0 == 0) {
        if (NELEM + 0 < out_size) out[NELEM + 0] = g_sums[0] / 8.0f;
        if (NELEM + 1 < out_size) out[NELEM + 1] = g_sums[1] / 8.0f;
        if (NELEM + 2 < out_size) out[NELEM + 2] = g_sums[2] / 8.0f;
    }
    if (t0 < NB * NIDX && NELEM + 3 + t0 < out_size)
        out[NELEM + 3 + t0] = (float)g_idxbuf[t0];
}

// ---------------- host ----------------
extern "C" void kernel_launch(void* const* d_in, const int* in_sizes, int n_in,
                              void* d_out, int out_size) {
    const float* z  = (const float*)d_in[0];
    const float* cb = (const float*)d_in[1];
    const float* pw = (const float*)d_in[2];
    const float* pb = (const float*)d_in[3];
    float* out = (float*)d_out;

    void *p_xa = 0, *p_xb = 0, *p_w = 0;
    cudaGetSymbolAddress(&p_xa, g_xs_a);
    cudaGetSymbolAddress(&p_xb, g_xs_b);
    cudaGetSymbolAddress(&p_w,  g_wsp);
    cudaFuncSetAttribute(conv_tc_kernel, cudaFuncAttributeMaxDynamicSharedMemorySize, CONV_SMEM);

    init_kernel<<<2048, 256>>>(z);
    wsplit_kernel<<<(int)((16ll * NC * NC + 255) / 256), 256>>>(pw);
    cnorm_kernel<<<NQ * NV, 128>>>(cb);

    for (int q = 0; q < NQ; q++) {
        int s = 1 << q, slog = q, M = NB * s;
        const float* cbq = cb + (long long)q * NV * NC;

        downsample_kernel<<<(NB * NC * s + 255) / 256, 256>>>(s, slog);

        if (s == 1)      quantize_small_kernel<1><<<dim3(64, 8), 256>>>(cbq, q);
        else if (s == 2) quantize_small_kernel<2><<<dim3(64, 8), 256>>>(cbq, q);
        else if (s == 4) quantize_small_kernel<4><<<dim3(64, 8), 256>>>(cbq, q);
        else if (s == 8) quantize_small_kernel<8><<<dim3(64, 8), 256>>>(cbq, q);
        else             quantize_gemm_kernel<<<dim3(M / 64, 8), 256>>>(cbq, q, s, slog);

        post_quantize_kernel<<<(M + 255) / 256, 256>>>(s, slog);
        upsample_split_kernel<<<dim3(NB, NT), 128>>>(cbq, s);

        const float* w0 = (const float*)p_w + ((long long)q * 2 + 0) * 6 * NC * NC;
        const float* w1 = (const float*)p_w + ((long long)q * 2 + 1) * 6 * NC * NC;
        const float* b0 = pb + ((long long)q * 2 + 0) * NC;
        const float* b1 = pb + ((long long)q * 2 + 1) * NC;
        conv_tc_kernel<<<dim3(4, NB), 256, CONV_SMEM>>>(
            (const float*)p_xa, w0, b0, (float*)p_xb, z, 0);
        conv_tc_kernel<<<dim3(4, NB), 256, CONV_SMEM>>>(
            (const float*)p_xb, w1, b1, (float*)0, z, 1);

        finalize_kernel<<<1, 1024>>>(s);
    }

    writeout_kernel<<<2048, 256>>>(out, out_size);
}

// round 6
// speedup vs baseline: 1.6497x; 1.2524x over previous
#include <cuda_runtime.h>
#include <math.h>

#define NB   64
#define NC   512
#define NT   128
#define NV   1024
#define NQ   8
#define NIDX 255
#define NELEM (NB*NC*NT)
#define PLANE ((long long)NB*NT*NC)

// ---------------- device scratch ----------------
__device__ float g_zq[NELEM];
__device__ float g_zhat[NELEM];
__device__ float g_xd[NB*NC*NT];
__device__ float g_xs_a[2ll*NB*NT*NC];   // conv1 input tf32 splits [2][b][t][ci]
__device__ float g_xs_b[2ll*NB*NT*NC];   // conv2 input tf32 splits
__device__ float g_wsp[16ll*6*NC*NC];    // [qd][split*3+tap][co][ci] tf32 values
__device__ float g_cnorm[NQ*NV];
__device__ unsigned long long g_bestkey[NB*NT];
__device__ int   g_idxbuf[NB*NIDX];
__device__ int   g_counts[NV];
__device__ float g_partial[256];
__device__ float g_sums[3];

// ---------------- tf32 split helpers ----------------
__device__ __forceinline__ float tf32r(float x) {
    unsigned u;
    asm("cvt.rna.tf32.f32 %0, %1;" : "=r"(u) : "f"(x));
    return __uint_as_float(u);
}
__device__ __forceinline__ void split2(float x, float& hi, float& lo) {
    hi = tf32r(x);
    lo = tf32r(x - hi);
}

// ---------------- f32x2 helpers (quantize gemm) ----------------
__device__ __forceinline__ unsigned long long dup2(float x) {
    unsigned long long r;
    asm("mov.b64 %0, {%1, %1};" : "=l"(r) : "f"(x));
    return r;
}
__device__ __forceinline__ void fma2(unsigned long long& a, unsigned long long x, unsigned long long y) {
    asm("fma.rn.f32x2 %0, %1, %2, %0;" : "+l"(a) : "l"(x), "l"(y));
}
__device__ __forceinline__ float2 unpack2(unsigned long long v) {
    float2 f;
    asm("mov.b64 {%0, %1}, %2;" : "=f"(f.x), "=f"(f.y) : "l"(v));
    return f;
}

// ---------------- init + cnorm (fused, launch 0) ----------------
__global__ void init_cnorm_kernel(const float* __restrict__ z, const float* __restrict__ cb) {
    if (blockIdx.x < 2048) {
        long long stride = 2048ll * 256;
        long long t0 = (long long)blockIdx.x * 256 + threadIdx.x;
        for (long long i = t0; i < NELEM; i += stride) { g_zq[i] = z[i]; g_zhat[i] = 0.0f; }
        if (t0 < 3)  g_sums[t0] = 0.0f;
        if (t0 < NV) g_counts[t0] = 0;
        if (t0 < NB*NT) g_bestkey[t0] = ~0ULL;
    } else {
        int row = blockIdx.x - 2048;
        const float* p = cb + (long long)row * NC;
        float s = 0.0f;
        for (int c = threadIdx.x; c < NC; c += 256) { float x = p[c]; s += x * x; }
        __shared__ float sh[8];
        for (int o = 16; o > 0; o >>= 1) s += __shfl_down_sync(0xffffffffu, s, o);
        if ((threadIdx.x & 31) == 0) sh[threadIdx.x >> 5] = s;
        __syncthreads();
        if (threadIdx.x == 0) {
            float t = 0.0f;
            for (int w = 0; w < 8; w++) t += sh[w];
            g_cnorm[row] = t;
        }
    }
}

// ---------------- weight split ----------------
__global__ void wsplit_kernel(const float* __restrict__ pw) {
    long long i = (long long)blockIdx.x * 256 + threadIdx.x;
    if (i >= 16ll * NC * NC) return;
    int qd = (int)(i >> 18);
    int r  = (int)(i & (NC*NC - 1));
    int co = r >> 9, ci = r & 511;
    const float* src = pw + (((long long)qd * NC + co) * NC + ci) * 3;
    float* dst = g_wsp + (long long)qd * 6 * NC * NC;
#pragma unroll
    for (int k = 0; k < 3; k++) {
        float hi, lo;
        split2(src[k], hi, lo);
        dst[(long long)k * NC * NC + co * NC + ci]       = hi;
        dst[(long long)(3 + k) * NC * NC + co * NC + ci] = lo;
    }
}

// ---------------- fused s=1: coalesced mean + quantize ----------------
__global__ __launch_bounds__(256) void quant_s1_kernel(const float* __restrict__ cb) {
    __shared__ float xs[512];
    int b  = blockIdx.x;
    int c0 = blockIdx.y * 128;
    int tid = threadIdx.x;
    int wp = tid >> 5, lane = tid & 31;

    // mean over t: warp per row group (coalesced float4)
    for (int i = 0; i < 64; i++) {
        int row = wp * 64 + i;
        float4 v = ((const float4*)(g_zq + (long long)(b * NC + row) * NT))[lane];
        float s = v.x + v.y + v.z + v.w;
        for (int o = 16; o > 0; o >>= 1) s += __shfl_xor_sync(0xffffffffu, s, o);
        if (lane == 0) xs[row] = s * (1.0f / 128.0f);
    }
    __syncthreads();

    float bestv = INFINITY;
    int besti = 0;
    for (int cc = 0; cc < 16; cc++) {
        int code = c0 + wp * 16 + cc;
        const float* cbr = cb + (long long)code * 512;
        float d = 0.0f;
#pragma unroll
        for (int e = 0; e < 16; e++) d += xs[lane + 32 * e] * cbr[lane + 32 * e];
        for (int o = 16; o > 0; o >>= 1) d += __shfl_xor_sync(0xffffffffu, d, o);
        float sc = g_cnorm[code] - 2.0f * d;
        if (sc < bestv) { bestv = sc; besti = code; }
    }
    if (lane == 0) {
        unsigned u = __float_as_uint(bestv);
        u = (u & 0x80000000u) ? ~u : (u | 0x80000000u);
        atomicMin(&g_bestkey[b], ((unsigned long long)u << 32) | (unsigned)besti);
    }
}

// ---------------- downsample: warp-per-output (s=2,4), thread (s>=8) ----------------
__global__ void downsample_warp_kernel(int s, int slog) {
    int r = NT >> slog;                 // 64 or 32
    int i = blockIdx.x * 8 + (threadIdx.x >> 5);
    int lane = threadIdx.x & 31;
    if (i >= NB * NC * s) return;
    int j  = i & (s - 1);
    int bc = i >> slog;
    const float* src = g_zq + (long long)bc * NT + j * r;
    float acc;
    if (r == 64) { float2 v = ((const float2*)src)[lane]; acc = v.x + v.y; }
    else         { acc = src[lane]; }
    for (int o = 16; o > 0; o >>= 1) acc += __shfl_xor_sync(0xffffffffu, acc, o);
    if (lane == 0) g_xd[i] = acc * (1.0f / (float)r);
}
__global__ void downsample_kernel(int s, int slog) {
    int total = NB * NC * s;
    int r = NT >> slog;
    int i = blockIdx.x * blockDim.x + threadIdx.x;
    if (i >= total) return;
    int j  = i & (s - 1);
    int bc = i >> slog;
    const float* src = g_zq + (long long)bc * NT + j * r;
    float acc = 0.0f;
    for (int k = 0; k < r; k++) acc += src[k];
    g_xd[i] = acc * (1.0f / (float)r);
}

// ---------------- quantize (s in 2..8) ----------------
template<int S>
__global__ __launch_bounds__(256) void quantize_small_kernel(const float* __restrict__ cb, int q) {
    __shared__ float xs[S][512];
    int b  = blockIdx.x;
    int c0 = blockIdx.y * 128;
    int tid = threadIdx.x;
    for (int e = tid; e < S * 512; e += 256) {
        int j = e >> 9, ch = e & 511;
        xs[j][ch] = g_xd[(b * 512 + ch) * S + j];
    }
    __syncthreads();
    int w = tid >> 5, lane = tid & 31;
    float bestv[S]; int besti[S];
#pragma unroll
    for (int j = 0; j < S; j++) { bestv[j] = INFINITY; besti[j] = 0; }
    for (int cc = 0; cc < 16; cc++) {
        int code = c0 + w * 16 + cc;
        const float* cbr = cb + (long long)code * 512;
        float cv[16];
#pragma unroll
        for (int e = 0; e < 16; e++) cv[e] = cbr[lane + 32 * e];
        float cn = g_cnorm[q * NV + code];
#pragma unroll
        for (int j = 0; j < S; j++) {
            float d = 0.0f;
#pragma unroll
            for (int e = 0; e < 16; e++) d += xs[j][lane + 32 * e] * cv[e];
            for (int o = 16; o > 0; o >>= 1) d += __shfl_xor_sync(0xffffffffu, d, o);
            float sc = cn - 2.0f * d;
            if (sc < bestv[j]) { bestv[j] = sc; besti[j] = code; }
        }
    }
    if (lane == 0) {
#pragma unroll
        for (int j = 0; j < S; j++) {
            unsigned u = __float_as_uint(bestv[j]);
            u = (u & 0x80000000u) ? ~u : (u | 0x80000000u);
            atomicMin(&g_bestkey[b * S + j], ((unsigned long long)u << 32) | (unsigned)besti[j]);
        }
    }
}

// ---------------- quantize (s>=16) ----------------
__global__ __launch_bounds__(256) void quantize_gemm_kernel(
    const float* __restrict__ cb, int q, int s, int slog)
{
    const int m0 = blockIdx.x * 64;
    const int n0 = blockIdx.y * 128;
    __shared__ float As[32][65];
    __shared__ float Bs[32][130];
    const int tid = threadIdx.x;
    const int ti = tid >> 4, tj = tid & 15;
    unsigned long long acc[4][4];
#pragma unroll
    for (int r = 0; r < 4; r++)
#pragma unroll
        for (int c = 0; c < 4; c++) acc[r][c] = 0ULL;
    for (int kc = 0; kc < NC; kc += 32) {
#pragma unroll
        for (int it = 0; it < 8; it++) {
            int e = tid + 256 * it;
            int m = e & 63, kk = e >> 6;
            int gm = m0 + m;
            int b = gm >> slog, j = gm & (s - 1);
            As[kk][m] = g_xd[(((long long)b * NC + (kc + kk)) << slog) + j];
        }
#pragma unroll
        for (int it = 0; it < 16; it++) {
            int e = tid + 256 * it;
            int kk = e & 31, n = e >> 5;
            Bs[kk][n] = cb[(long long)(n0 + n) * NC + kc + kk];
        }
        __syncthreads();
#pragma unroll 8
        for (int kk = 0; kk < 32; kk++) {
            unsigned long long a2[4], b2[4];
#pragma unroll
            for (int r = 0; r < 4; r++) a2[r] = dup2(As[kk][ti + 16 * r]);
#pragma unroll
            for (int c = 0; c < 4; c++) b2[c] = *(const unsigned long long*)&Bs[kk][2 * tj + 32 * c];
#pragma unroll
            for (int r = 0; r < 4; r++)
#pragma unroll
                for (int c = 0; c < 4; c++) fma2(acc[r][c], a2[r], b2[c]);
        }
        __syncthreads();
    }
    float bestv[4]; int besti[4];
#pragma unroll
    for (int r = 0; r < 4; r++) { bestv[r] = INFINITY; besti[r] = 0; }
#pragma unroll
    for (int c = 0; c < 4; c++) {
        int n = n0 + 2 * tj + 32 * c;
        float cn0 = g_cnorm[q * NV + n], cn1 = g_cnorm[q * NV + n + 1];
#pragma unroll
        for (int r = 0; r < 4; r++) {
            float2 dv = unpack2(acc[r][c]);
            float s0 = cn0 - 2.0f * dv.x, s1 = cn1 - 2.0f * dv.y;
            if (s0 < bestv[r]) { bestv[r] = s0; besti[r] = n; }
            if (s1 < bestv[r]) { bestv[r] = s1; besti[r] = n + 1; }
        }
    }
#pragma unroll
    for (int r = 0; r < 4; r++) {
        float v = bestv[r]; int ix = besti[r];
        for (int off = 8; off > 0; off >>= 1) {
            float ov = __shfl_down_sync(0xffffffffu, v, off, 16);
            int   oi = __shfl_down_sync(0xffffffffu, ix, off, 16);
            if (ov < v || (ov == v && oi < ix)) { v = ov; ix = oi; }
        }
        if (tj == 0) {
            unsigned u = __float_as_uint(v);
            u = (u & 0x80000000u) ? ~u : (u | 0x80000000u);
            atomicMin(&g_bestkey[m0 + ti + 16 * r], ((unsigned long long)u << 32) | (unsigned)ix);
        }
    }
}

// ---------------- extract idx + histogram ----------------
__global__ void post_quantize_kernel(int s, int slog) {
    int m = blockIdx.x * blockDim.x + threadIdx.x;
    if (m >= NB * s) return;
    int v = (int)(g_bestkey[m] & 0xFFFFFFFFULL);
    int b = m >> slog, j = m & (s - 1);
    g_idxbuf[b * NIDX + (s - 1) + j] = v;
    atomicAdd(&g_counts[v], 1);
}

// ---------------- upsample -> tf32 splits [2][b][t][ci] ----------------
__global__ void upsample_split_kernel(const float* __restrict__ cb, int s) {
    int b = blockIdx.x, t = blockIdx.y;
    float u = (t + 0.5f) * ((float)s / 128.0f) - 0.5f;
    float jf = floorf(u);
    float f = u - jf;
    int j0 = (int)jf, j1 = j0 + 1;
    if (j0 < 0) j0 = 0; if (j0 > s - 1) j0 = s - 1;
    if (j1 < 0) j1 = 0; if (j1 > s - 1) j1 = s - 1;
    int v0 = g_idxbuf[b * NIDX + (s - 1) + j0];
    int v1 = g_idxbuf[b * NIDX + (s - 1) + j1];
    const float* c0 = cb + (long long)v0 * NC;
    const float* c1 = cb + (long long)v1 * NC;
    float w1 = f, w0 = 1.0f - f;
    long long base = ((long long)(b * NT + t)) * NC;
    for (int c = threadIdx.x; c < NC; c += 128) {
        float val = w0 * c0[c] + w1 * c1[c];
        float hi, lo;
        split2(val, hi, lo);
        g_xs_a[base + c]         = hi;
        g_xs_a[base + c + PLANE] = lo;
    }
}

// ---------------- tensor-core conv via mma.sync tf32, 3 split terms ----------------
#define CONV_SMEM (24672*4)
__global__ __launch_bounds__(256) void conv_tc_kernel(
    const float* __restrict__ xs,   // [2][b][t][ci]
    const float* __restrict__ wsp,  // [6][co][ci] for this layer
    const float* __restrict__ bias,
    float* __restrict__ ys,         // conv1 out splits (fuse=0)
    const float* __restrict__ z, int fuse)
{
    extern __shared__ float sm[];
    const int tid = threadIdx.x, lane = tid & 31, wp = tid >> 5;
    const int cg = wp >> 2, tg = wp & 3;
    const int b = blockIdx.y, co0 = blockIdx.x * 128;
    const int lq = lane >> 2, lr = lane & 3;

    float acc[4][4][4];
#pragma unroll
    for (int mt = 0; mt < 4; mt++)
#pragma unroll
        for (int nt = 0; nt < 4; nt++)
#pragma unroll
            for (int r = 0; r < 4; r++) acc[mt][nt][r] = 0.0f;

    for (int ch = 0; ch < 32; ch++) {
        int ci0 = ch * 16;
        // ---- load X tiles (2 splits, 130 halo rows x 16 ci) ----
        for (int e = tid; e < 1040; e += 256) {
            int sp = (e >= 520);
            int r = e - sp * 520;
            int row = r >> 2, q = r & 3;
            int t = row - 1;
            float4 v = make_float4(0.f, 0.f, 0.f, 0.f);
            if ((unsigned)t < 128u)
                v = *(const float4*)(xs + sp * PLANE + ((long long)(b * NT + t)) * NC + ci0 + q * 4);
            float* dst = sm + sp * 3120 + row * 24;
            const float* pv = (const float*)&v;
#pragma unroll
            for (int li = 0; li < 4; li++) {
                int lc = q * 4 + li;
                int c = lc & 7;
                dst[((lc >> 3) << 3) + ((c & 3) << 1) + (c >> 2)] = pv[li];
            }
        }
        // ---- load W tiles (6 = split*3+tap) ----
        for (int e = tid; e < 3072; e += 256) {
            int tile = e >> 9;
            int r = e & 511;
            int row = r >> 2, q = r & 3;
            float4 v = *(const float4*)(wsp + (long long)tile * (NC * NC)
                                        + (long long)(co0 + row) * NC + ci0 + q * 4);
            float* dst = sm + 6240 + tile * 3072 + row * 24;
            const float* pv = (const float*)&v;
#pragma unroll
            for (int li = 0; li < 4; li++) {
                int lc = q * 4 + li;
                int c = lc & 7;
                dst[((lc >> 3) << 3) + ((c & 3) << 1) + (c >> 2)] = pv[li];
            }
        }
        __syncthreads();
        // ---- 3 terms: (whi,xhi), (whi,xlo), (wlo,xhi); A loaded once per (wa,tap,k8) ----
#pragma unroll
        for (int wa = 0; wa < 2; wa++) {
            const int nxb = (wa == 0) ? 2 : 1;
            for (int tap = 0; tap < 3; tap++) {
                const float* Wt = sm + 6240 + (wa * 3 + tap) * 3072;
#pragma unroll
                for (int k8 = 0; k8 < 2; k8++) {
                    unsigned a[4][4];
#pragma unroll
                    for (int mt = 0; mt < 4; mt++) {
                        int row = cg * 64 + mt * 16 + lq;
                        uint2 p0 = *(const uint2*)&Wt[row * 24 + k8 * 8 + lr * 2];
                        uint2 p1 = *(const uint2*)&Wt[(row + 8) * 24 + k8 * 8 + lr * 2];
                        a[mt][0] = p0.x; a[mt][2] = p0.y;
                        a[mt][1] = p1.x; a[mt][3] = p1.y;
                    }
#pragma unroll
                    for (int xb = 0; xb < 2; xb++) {
                        if (xb >= nxb) break;
                        const float* Xt = sm + xb * 3120;
#pragma unroll
                        for (int nt = 0; nt < 4; nt++) {
                            int trow = tg * 32 + nt * 8 + lq + tap;
                            uint2 bb = *(const uint2*)&Xt[trow * 24 + k8 * 8 + lr * 2];
#pragma unroll
                            for (int mt = 0; mt < 4; mt++) {
                                asm volatile(
                                    "mma.sync.aligned.m16n8k8.row.col.f32.tf32.tf32.f32 "
                                    "{%0,%1,%2,%3}, {%4,%5,%6,%7}, {%8,%9}, {%0,%1,%2,%3};"
                                    : "+f"(acc[mt][nt][0]), "+f"(acc[mt][nt][1]),
                                      "+f"(acc[mt][nt][2]), "+f"(acc[mt][nt][3])
                                    : "r"(a[mt][0]), "r"(a[mt][1]), "r"(a[mt][2]), "r"(a[mt][3]),
                                      "r"(bb.x), "r"(bb.y));
                            }
                        }
                    }
                }
            }
        }
        __syncthreads();
    }

    // ---- epilogue ----
    if (!fuse) {
#pragma unroll
        for (int mt = 0; mt < 4; mt++)
#pragma unroll
            for (int nt = 0; nt < 4; nt++) {
                int row = cg * 64 + mt * 16 + lq;
                int t0 = tg * 32 + nt * 8 + lr * 2;
                sm[t0 * 130 + row]           = acc[mt][nt][0];
                sm[(t0 + 1) * 130 + row]     = acc[mt][nt][1];
                sm[t0 * 130 + row + 8]       = acc[mt][nt][2];
                sm[(t0 + 1) * 130 + row + 8] = acc[mt][nt][3];
            }
        __syncthreads();
        for (int e = tid; e < 16384; e += 256) {
            int t = e >> 7, co = e & 127;
            float v = fmaxf(sm[t * 130 + co] + bias[co0 + co], 0.0f);
            float hi, lo;
            split2(v, hi, lo);
            long long o = ((long long)(b * NT + t)) * NC + co0 + co;
            ys[o]         = hi;
            ys[o + PLANE] = lo;
        }
    } else {
        float lsum = 0.0f;
#pragma unroll
        for (int mt = 0; mt < 4; mt++)
#pragma unroll
            for (int nt = 0; nt < 4; nt++) {
                int row = cg * 64 + mt * 16 + lq;
                int t0 = tg * 32 + nt * 8 + lr * 2;
#pragma unroll
                for (int h = 0; h < 2; h++) {
                    int co = co0 + row + h * 8;
                    float bv = bias[co];
                    float y0 = fmaxf(acc[mt][nt][h * 2 + 0] + bv, 0.0f);
                    float y1 = fmaxf(acc[mt][nt][h * 2 + 1] + bv, 0.0f);
                    long long i = ((long long)(b * NC + co)) * NT + t0;
                    float2 zh  = *(float2*)&g_zhat[i];
                    float2 zz  = *(const float2*)&z[i];
                    float2 zqv = *(float2*)&g_zq[i];
                    zh.x += y0; zh.y += y1;
                    *(float2*)&g_zhat[i] = zh;
                    zqv.x -= y0; zqv.y -= y1;
                    *(float2*)&g_zq[i] = zqv;
                    float d0 = zh.x - zz.x, d1 = zh.y - zz.y;
                    lsum += d0 * d0 + d1 * d1;
                }
            }
        __syncthreads();
        for (int o = 16; o > 0; o >>= 1) lsum += __shfl_down_sync(0xffffffffu, lsum, o);
        if ((tid & 31) == 0) sm[tid >> 5] = lsum;
        __syncthreads();
        if (tid == 0) {
            float s = 0.0f;
#pragma unroll
            for (int i2 = 0; i2 < 8; i2++) s += sm[i2];
            g_partial[blockIdx.y * 4 + blockIdx.x] = s;
        }
    }
}

// ---------------- per-scale finalize ----------------
__global__ void finalize_kernel(int s) {
    __shared__ float sh[32];
    int tid = threadIdx.x;
    float lsum = (tid < 256) ? g_partial[tid] : 0.0f;
    for (int o = 16; o > 0; o >>= 1) lsum += __shfl_down_sync(0xffffffffu, lsum, o);
    if ((tid & 31) == 0) sh[tid >> 5] = lsum;
    __syncthreads();
    float loss_total = 0.0f;
    if (tid == 0) for (int w = 0; w < 32; w++) loss_total += sh[w];
    __syncthreads();
    int c = g_counts[tid];
    float used = (c > 0) ? 1.0f : 0.0f;
    float p = (float)c / (float)(NB * s);
    float ent = p * logf(p + 1e-10f);
    float us = used;
    for (int o = 16; o > 0; o >>= 1) us += __shfl_down_sync(0xffffffffu, us, o);
    if ((tid & 31) == 0) sh[tid >> 5] = us;
    __syncthreads();
    float used_total = 0.0f;
    if (tid == 0) for (int w = 0; w < 32; w++) used_total += sh[w];
    __syncthreads();
    float es = ent;
    for (int o = 16; o > 0; o >>= 1) es += __shfl_down_sync(0xffffffffu, es, o);
    if ((tid & 31) == 0) sh[tid >> 5] = es;
    __syncthreads();
    float ent_total = 0.0f;
    if (tid == 0) for (int w = 0; w < 32; w++) ent_total += sh[w];
    if (tid == 0) {
        g_sums[0] += used_total * (100.0f / (float)NV);
        g_sums[1] += 1.25f * loss_total / (float)NELEM;
        g_sums[2] += expf(-ent_total);
    }
    g_counts[tid] = 0;
    for (int i = tid; i < NB * NT; i += 1024) g_bestkey[i] = ~0ULL;
}

// ---------------- write outputs ----------------
__global__ void writeout_kernel(float* __restrict__ out, int out_size) {
    long long stride = (long long)gridDim.x * blockDim.x;
    long long t0 = (long long)blockIdx.x * blockDim.x + threadIdx.x;
    for (long long i = t0; i < NELEM && i < out_size; i += stride) out[i] = g_zhat[i];
    if (t0 == 0) {
        if (NELEM + 0 < out_size) out[NELEM + 0] = g_sums[0] / 8.0f;
        if (NELEM + 1 < out_size) out[NELEM + 1] = g_sums[1] / 8.0f;
        if (NELEM + 2 < out_size) out[NELEM + 2] = g_sums[2] / 8.0f;
    }
    if (t0 < NB * NIDX && NELEM + 3 + t0 < out_size)
        out[NELEM + 3 + t0] = (float)g_idxbuf[t0];
}

// ---------------- host ----------------
extern "C" void kernel_launch(void* const* d_in, const int* in_sizes, int n_in,
                              void* d_out, int out_size) {
    const float* z  = (const float*)d_in[0];
    const float* cb = (const float*)d_in[1];
    const float* pw = (const float*)d_in[2];
    const float* pb = (const float*)d_in[3];
    float* out = (float*)d_out;

    void *p_xa = 0, *p_xb = 0, *p_w = 0;
    cudaGetSymbolAddress(&p_xa, g_xs_a);
    cudaGetSymbolAddress(&p_xb, g_xs_b);
    cudaGetSymbolAddress(&p_w,  g_wsp);
    cudaFuncSetAttribute(conv_tc_kernel, cudaFuncAttributeMaxDynamicSharedMemorySize, CONV_SMEM);

    init_cnorm_kernel<<<2048 + NQ * NV, 256>>>(z, cb);       // launch 0
    wsplit_kernel<<<(int)((16ll * NC * NC + 255) / 256), 256>>>(pw);  // launch 1

    for (int q = 0; q < NQ; q++) {
        int s = 1 << q, slog = q, M = NB * s;
        const float* cbq = cb + (long long)q * NV * NC;

        if (s == 1) {
            quant_s1_kernel<<<dim3(64, 8), 256>>>(cbq);                       // launch 2
        } else if (s <= 4) {
            downsample_warp_kernel<<<(NB * NC * s) / 8, 256>>>(s, slog);
            if (s == 2) quantize_small_kernel<2><<<dim3(64, 8), 256>>>(cbq, q);
            else        quantize_small_kernel<4><<<dim3(64, 8), 256>>>(cbq, q);
        } else {
            downsample_kernel<<<(NB * NC * s + 255) / 256, 256>>>(s, slog);
            if (s == 8) quantize_small_kernel<8><<<dim3(64, 8), 256>>>(cbq, q);
            else        quantize_gemm_kernel<<<dim3(M / 64, 8), 256>>>(cbq, q, s, slog);
        }

        post_quantize_kernel<<<(M + 255) / 256, 256>>>(s, slog);              // q=0: launch 3
        upsample_split_kernel<<<dim3(NB, NT), 128>>>(cbq, s);                 // q=0: launch 4

        const float* w0 = (const float*)p_w + ((long long)q * 2 + 0) * 6 * NC * NC;
        const float* w1 = (const float*)p_w + ((long long)q * 2 + 1) * 6 * NC * NC;
        const float* b0 = pb + ((long long)q * 2 + 0) * NC;
        const float* b1 = pb + ((long long)q * 2 + 1) * NC;
        conv_tc_kernel<<<dim3(4, NB), 256, CONV_SMEM>>>(
            (const float*)p_xa, w0, b0, (float*)p_xb, z, 0);                  // q=0: launch 5  <-- profiled
        conv_tc_kernel<<<dim3(4, NB), 256, CONV_SMEM>>>(
            (const float*)p_xb, w1, b1, (float*)0, z, 1);

        finalize_kernel<<<1, 1024>>>(s);
    }

    writeout_kernel<<<2048, 256>>>(out, out_size);
}